// round 8
// baseline (speedup 1.0000x reference)
#include <cuda_runtime.h>

// GAT over 16384 independent 32-node cliques, fully fused: one CTA per graph.
// = Round-6 base (bank-exact tiles + fp32x2 packed math, smem-based attention
//   scores at the LDS data floor)
// + beta-collapsed tail: out = (sum_j beta[j] h3[j] + b3) @ lw + lb with
//   beta[j] = mean_n alpha3[n][j]  (deletes the per-node layer-3 aggregation).

#define NCOL 32
#define HEADS 4
#define FH 128          // H * HID
#define FHP 132         // padded h row; consecutive rows conflict-free for f4
#define F3 24           // H * OUT
#define XINP 20
#define THREADS 128
#define NEG_SLOPE 0.2f

typedef unsigned long long u64;

__device__ float W3p_g[FH * 32];   // W3 padded: [f][head*8+d], zeros at d=6,7
__device__ float as3p_g[32];       // a_src3 padded [head*8+d]
__device__ float ad3p_g[32];       // a_dst3 padded

__device__ __forceinline__ float lrelu(float x) { return x > 0.f ? x : NEG_SLOPE * x; }

__device__ __forceinline__ u64 dup2(float x) {
    u64 r; asm("mov.b64 %0,{%1,%1};" : "=l"(r) : "f"(x)); return r;
}
__device__ __forceinline__ u64 pack2(float a, float b) {
    u64 r; asm("mov.b64 %0,{%1,%2};" : "=l"(r) : "f"(a), "f"(b)); return r;
}
__device__ __forceinline__ float2 unpack2(u64 v) {
    float2 r; asm("mov.b64 {%0,%1},%2;" : "=f"(r.x), "=f"(r.y) : "l"(v)); return r;
}
__device__ __forceinline__ void fma2(u64 &d, u64 a, u64 b) {
    asm("fma.rn.f32x2 %0,%1,%2,%0;" : "+l"(d) : "l"(a), "l"(b));
}
__device__ __forceinline__ void add2(u64 &d, u64 a) {
    asm("add.rn.f32x2 %0,%0,%1;" : "+l"(d) : "l"(a));
}
__device__ __forceinline__ u64 shfl_xor_u64(u64 v, int m) {
    unsigned lo, hi;
    asm("mov.b64 {%0,%1},%2;" : "=r"(lo), "=r"(hi) : "l"(v));
    lo = __shfl_xor_sync(0xffffffffu, lo, m);
    hi = __shfl_xor_sync(0xffffffffu, hi, m);
    u64 r; asm("mov.b64 %0,{%1,%2};" : "=l"(r) : "r"(lo), "r"(hi));
    return r;
}

__global__ void prep_kernel(const float* __restrict__ W3,
                            const float* __restrict__ as3,
                            const float* __restrict__ ad3) {
    int idx = blockIdx.x * blockDim.x + threadIdx.x;
    if (idx < FH * 32) {
        int f = idx >> 5, hp = idx & 31, d = hp & 7, h = hp >> 3;
        W3p_g[idx] = (d < 6) ? W3[f * F3 + h * 6 + d] : 0.f;
    } else if (idx < FH * 32 + 32) {
        int i = idx - FH * 32, h = i >> 3, d = i & 7;
        as3p_g[i] = (d < 6) ? as3[h * 6 + d] : 0.f;
    } else if (idx < FH * 32 + 64) {
        int i = idx - FH * 32 - 32, h = i >> 3, d = i & 7;
        ad3p_g[i] = (d < 6) ? ad3[h * 6 + d] : 0.f;
    }
}

// ---- attention for D=32 heads (layers 1 & 2), in-place on h (Round-6) ----
__device__ __forceinline__ void gat_attention32(
    float (*__restrict__ h)[FHP],
    const float* __restrict__ a_src, const float* __restrict__ a_dst,
    const float* __restrict__ bias,
    float* __restrict__ s_src, float* __restrict__ s_dst,
    float (*__restrict__ alpha)[NCOL], int t)
{
    const int head = t >> 5;
    const int lane = t & 31;
    const int c0 = head * 32;

    // phase 1: scores for node n = lane (k-packed; at the LDS data floor)
    {
        const ulonglong2* hp = (const ulonglong2*)&h[lane][c0];
        const ulonglong2* ap = (const ulonglong2*)(a_src + c0);
        const ulonglong2* dp = (const ulonglong2*)(a_dst + c0);
        u64 ss2 = 0, sd2 = 0;
#pragma unroll
        for (int q = 0; q < 8; q++) {
            ulonglong2 hq = hp[q];
            ulonglong2 aq = ap[q];
            ulonglong2 dq = dp[q];
            fma2(ss2, hq.x, aq.x); fma2(ss2, hq.y, aq.y);
            fma2(sd2, hq.x, dq.x); fma2(sd2, hq.y, dq.y);
        }
        float2 s2 = unpack2(ss2);
        float2 d2 = unpack2(sd2);
        s_src[head * NCOL + lane] = s2.x + s2.y;
        s_dst[head * NCOL + lane] = d2.x + d2.y;
    }
    __syncwarp();

    // phase 2: softmax; store rotated, rinv-scaled alpha
    {
        const float sdst = s_dst[head * NCOL + lane];
        float e[NCOL];
        float m = -1e30f;
#pragma unroll
        for (int q = 0; q < 8; q++) {
            float4 sv = *(const float4*)&s_src[head * NCOL + 4 * q];
            e[4*q+0] = lrelu(sdst + sv.x);
            e[4*q+1] = lrelu(sdst + sv.y);
            e[4*q+2] = lrelu(sdst + sv.z);
            e[4*q+3] = lrelu(sdst + sv.w);
        }
#pragma unroll
        for (int j = 0; j < NCOL; j++) m = fmaxf(m, e[j]);
        float sum = 0.f;
#pragma unroll
        for (int j = 0; j < NCOL; j++) {
            e[j] = __expf(e[j] - m);
            sum += e[j];
        }
        const float rinv = 1.f / sum;
        const int rot = lane >> 2;
#pragma unroll
        for (int q = 0; q < 8; q++) {
            int col = ((q + rot) & 7) * 4;
            float4 v;
            v.x = e[4*q+0] * rinv;
            v.y = e[4*q+1] * rinv;
            v.z = e[4*q+2] * rinv;
            v.w = e[4*q+3] * rinv;
            *(float4*)&alpha[lane][col] = v;
        }
    }
    __syncwarp();

    // phase 3: out(32x32) = alpha @ h_head (channel-packed)
    const int ng = lane >> 2;
    const int cg = lane & 3;
    const int cb = c0 + 8 * cg;
    u64 acc2[4][4];
#pragma unroll
    for (int i = 0; i < 4; i++)
#pragma unroll
        for (int p = 0; p < 4; p++) acc2[i][p] = 0;

#pragma unroll
    for (int j0 = 0; j0 < NCOL; j0 += 4) {
        float4 av[4];
        const int colb = (((j0 >> 2) + ng) & 7) * 4;
#pragma unroll
        for (int i = 0; i < 4; i++)
            av[i] = *(const float4*)&alpha[4 * ng + i][colb];
#pragma unroll
        for (int jj = 0; jj < 4; jj++) {
            ulonglong2 h0 = *(const ulonglong2*)&h[j0 + jj][cb];
            ulonglong2 h1 = *(const ulonglong2*)&h[j0 + jj][cb + 4];
#pragma unroll
            for (int i = 0; i < 4; i++) {
                u64 a = dup2(((const float*)&av[i])[jj]);
                fma2(acc2[i][0], a, h0.x);
                fma2(acc2[i][1], a, h0.y);
                fma2(acc2[i][2], a, h1.x);
                fma2(acc2[i][3], a, h1.y);
            }
        }
    }
    __syncthreads();   // everyone done reading h before in-place overwrite

    ulonglong2 b01 = *(const ulonglong2*)&bias[cb];
    ulonglong2 b23 = *(const ulonglong2*)&bias[cb + 4];
#pragma unroll
    for (int i = 0; i < 4; i++) {
        int row = 4 * ng + i;
        u64 o0 = acc2[i][0], o1 = acc2[i][1], o2 = acc2[i][2], o3 = acc2[i][3];
        add2(o0, b01.x); add2(o1, b01.y); add2(o2, b23.x); add2(o3, b23.y);
        ulonglong2 s0; s0.x = o0; s0.y = o1;
        ulonglong2 s1; s1.x = o2; s1.y = o3;
        *(ulonglong2*)&h[row][cb]     = s0;
        *(ulonglong2*)&h[row][cb + 4] = s1;
    }
    __syncthreads();
}

__global__ void __launch_bounds__(THREADS, 6) gat_fused_kernel(
    const float* __restrict__ xs,
    const float* __restrict__ pe,
    const float* __restrict__ W1,
    const float* __restrict__ as1, const float* __restrict__ ad1,
    const float* __restrict__ b1,
    const float* __restrict__ W2,
    const float* __restrict__ as2, const float* __restrict__ ad2,
    const float* __restrict__ b2,
    const float* __restrict__ b3,
    const float* __restrict__ lw,
    const float* __restrict__ lb,
    float* __restrict__ out,
    int R)
{
    __shared__ float hs[NCOL][FHP];
    __shared__ float alphas[HEADS][NCOL][NCOL];
    __shared__ float s_src[HEADS * NCOL];
    __shared__ float s_dst[HEADS * NCOL];
    __shared__ float xin[NCOL][XINP];
    __shared__ float ys[F3];

    const int g = blockIdx.x;
    const int b = g / R;
    const int r = g - b * R;
    const int t = threadIdx.x;
    const int lane = t & 31;
    const int w = t >> 5;
    const int cq = lane & 7;
    const int ngrp = lane >> 3;

    // ---- build input features ----
    for (int idx = t; idx < NCOL * 16; idx += THREADS) {
        int n = idx >> 4, f = idx & 15;
        float v;
        if (f == 0) v = xs[(size_t)(b * R + r) * NCOL + n];
        else        v = pe[(b * NCOL + n) * 15 + (f - 1)];
        xin[n][f] = v;
    }
    __syncthreads();

    // ---- layer 1 GEMM: warp w -> channels 32w..32w+31 (channel-packed) ----
    {
        const int cwb = 32 * w;
        u64 acc2[8][2];
#pragma unroll
        for (int nn = 0; nn < 8; nn++) { acc2[nn][0] = 0; acc2[nn][1] = 0; }
#pragma unroll
        for (int f0 = 0; f0 < 16; f0 += 4) {
            ulonglong2 wv[4];
#pragma unroll
            for (int k = 0; k < 4; k++)
                wv[k] = *(const ulonglong2*)(W1 + (f0 + k) * FH + cwb + 4 * cq);
#pragma unroll
            for (int nn = 0; nn < 8; nn++) {
                float4 hv = *(const float4*)&xin[4 * nn + ngrp][f0];
                u64 d0 = dup2(hv.x), d1 = dup2(hv.y), d2 = dup2(hv.z), d3 = dup2(hv.w);
                fma2(acc2[nn][0], d0, wv[0].x); fma2(acc2[nn][1], d0, wv[0].y);
                fma2(acc2[nn][0], d1, wv[1].x); fma2(acc2[nn][1], d1, wv[1].y);
                fma2(acc2[nn][0], d2, wv[2].x); fma2(acc2[nn][1], d2, wv[2].y);
                fma2(acc2[nn][0], d3, wv[3].x); fma2(acc2[nn][1], d3, wv[3].y);
            }
        }
#pragma unroll
        for (int nn = 0; nn < 8; nn++) {
            ulonglong2 o; o.x = acc2[nn][0]; o.y = acc2[nn][1];
            *(ulonglong2*)&hs[4 * nn + ngrp][cwb + 4 * cq] = o;
        }
    }
    __syncthreads();
    gat_attention32(hs, as1, ad1, b1, s_src, s_dst, alphas[w], t);

    // ---- layer 2 GEMM: warp w -> channels 32w..32w+31 (channel-packed) ----
    {
        const int cwb = 32 * w;
        u64 acc2[8][2];
#pragma unroll
        for (int nn = 0; nn < 8; nn++) { acc2[nn][0] = 0; acc2[nn][1] = 0; }

#pragma unroll 2
        for (int f0 = 0; f0 < FH; f0 += 4) {
            ulonglong2 wv[4];
#pragma unroll
            for (int k = 0; k < 4; k++)
                wv[k] = *(const ulonglong2*)(W2 + (f0 + k) * FH + cwb + 4 * cq);
#pragma unroll
            for (int nn = 0; nn < 8; nn++) {
                float4 hv = *(const float4*)&hs[4 * nn + ngrp][f0];   // 4 consec rows: 1 wf
                u64 d0 = dup2(hv.x), d1 = dup2(hv.y), d2 = dup2(hv.z), d3 = dup2(hv.w);
                fma2(acc2[nn][0], d0, wv[0].x); fma2(acc2[nn][1], d0, wv[0].y);
                fma2(acc2[nn][0], d1, wv[1].x); fma2(acc2[nn][1], d1, wv[1].y);
                fma2(acc2[nn][0], d2, wv[2].x); fma2(acc2[nn][1], d2, wv[2].y);
                fma2(acc2[nn][0], d3, wv[3].x); fma2(acc2[nn][1], d3, wv[3].y);
            }
        }
        __syncthreads();   // all reads of hs complete before overwrite
#pragma unroll
        for (int nn = 0; nn < 8; nn++) {
            ulonglong2 o; o.x = acc2[nn][0]; o.y = acc2[nn][1];
            *(ulonglong2*)&hs[4 * nn + ngrp][cwb + 4 * cq] = o;
        }
    }
    __syncthreads();
    gat_attention32(hs, as2, ad2, b2, s_src, s_dst, alphas[w], t);

    // ---- layer 3 GEMM: warp w -> nodes 8w..8w+7, 32 padded channels ----
    {
        u64 acc2[2][2];
        acc2[0][0] = acc2[0][1] = acc2[1][0] = acc2[1][1] = 0;

#pragma unroll 4
        for (int f0 = 0; f0 < FH; f0 += 4) {
            ulonglong2 wv[4];
#pragma unroll
            for (int k = 0; k < 4; k++)
                wv[k] = *(const ulonglong2*)(W3p_g + (f0 + k) * 32 + 4 * cq);
#pragma unroll
            for (int s = 0; s < 2; s++) {
                float4 hv = *(const float4*)&hs[8 * w + 4 * s + ngrp][f0];
                u64 d0 = dup2(hv.x), d1 = dup2(hv.y), d2 = dup2(hv.z), d3 = dup2(hv.w);
                fma2(acc2[s][0], d0, wv[0].x); fma2(acc2[s][1], d0, wv[0].y);
                fma2(acc2[s][0], d1, wv[1].x); fma2(acc2[s][1], d1, wv[1].y);
                fma2(acc2[s][0], d2, wv[2].x); fma2(acc2[s][1], d2, wv[2].y);
                fma2(acc2[s][0], d3, wv[3].x); fma2(acc2[s][1], d3, wv[3].y);
            }
        }
#pragma unroll
        for (int s = 0; s < 2; s++) {
            ulonglong2 o; o.x = acc2[s][0]; o.y = acc2[s][1];
            *(ulonglong2*)&hs[8 * w + 4 * s + ngrp][4 * cq] = o;
        }
    }
    __syncthreads();   // h3 visible cross-warp

    // ---- layer-3 attention, beta-collapsed tail ----
    {
        const int cp = 8 * w;   // padded col base for head w

        // phase 1: scores for node n = lane (cheap padded reads)
        {
            float4 hv0 = *(const float4*)&hs[lane][cp];
            float2 hv1 = *(const float2*)&hs[lane][cp + 4];
            float4 a0 = *(const float4*)&as3p_g[cp];
            float2 a1 = *(const float2*)&as3p_g[cp + 4];
            float4 d0 = *(const float4*)&ad3p_g[cp];
            float2 d1 = *(const float2*)&ad3p_g[cp + 4];
            float ss = fmaf(hv0.x, a0.x, fmaf(hv0.y, a0.y, fmaf(hv0.z, a0.z,
                       fmaf(hv0.w, a0.w, fmaf(hv1.x, a1.x, hv1.y * a1.y)))));
            float sd = fmaf(hv0.x, d0.x, fmaf(hv0.y, d0.y, fmaf(hv0.z, d0.z,
                       fmaf(hv0.w, d0.w, fmaf(hv1.x, d1.x, hv1.y * d1.y)))));
            s_src[w * NCOL + lane] = ss;
            s_dst[w * NCOL + lane] = sd;
        }
        __syncwarp();

        // phase 2: softmax for target n = lane; rotated alpha store
        {
            const float sdst = s_dst[w * NCOL + lane];
            float e[NCOL];
            float m = -1e30f;
#pragma unroll
            for (int q = 0; q < 8; q++) {
                float4 sv = *(const float4*)&s_src[w * NCOL + 4 * q];
                e[4*q+0] = lrelu(sdst + sv.x);
                e[4*q+1] = lrelu(sdst + sv.y);
                e[4*q+2] = lrelu(sdst + sv.z);
                e[4*q+3] = lrelu(sdst + sv.w);
            }
#pragma unroll
            for (int j = 0; j < NCOL; j++) m = fmaxf(m, e[j]);
            float sum = 0.f;
#pragma unroll
            for (int j = 0; j < NCOL; j++) {
                e[j] = __expf(e[j] - m);
                sum += e[j];
            }
            const float rinv = 1.f / sum;
            const int rot = lane >> 2;
#pragma unroll
            for (int q = 0; q < 8; q++) {
                int col = ((q + rot) & 7) * 4;
                float4 v;
                v.x = e[4*q+0] * rinv;
                v.y = e[4*q+1] * rinv;
                v.z = e[4*q+2] * rinv;
                v.w = e[4*q+3] * rinv;
                *(float4*)&alphas[w][lane][col] = v;
            }
        }
        __syncwarp();

        // beta[j] = mean_n alpha[n][j]  (rotated transpose read, lane = j)
        float beta = 0.f;
        const int jq = lane >> 2, jr = lane & 3;
#pragma unroll 8
        for (int n = 0; n < NCOL; n++)
            beta += alphas[w][n][(((jq + (n >> 2)) & 7) << 2) + jr];
        beta *= (1.f / 32.f);

        // y_head = sum_j beta[j] * h3[j][head cols], butterfly-reduced
        float4 hv0 = *(const float4*)&hs[lane][cp];
        float2 hv1 = *(const float2*)&hs[lane][cp + 4];
        u64 p0 = pack2(beta * hv0.x, beta * hv0.y);
        u64 p1 = pack2(beta * hv0.z, beta * hv0.w);
        u64 p2 = pack2(beta * hv1.x, beta * hv1.y);
#pragma unroll
        for (int off = 16; off >= 1; off >>= 1) {
            add2(p0, shfl_xor_u64(p0, off));
            add2(p1, shfl_xor_u64(p1, off));
            add2(p2, shfl_xor_u64(p2, off));
        }
        if (lane == 0) {
            float2 a = unpack2(p0), bb = unpack2(p1), c = unpack2(p2);
            ys[w * 6 + 0] = a.x  + b3[w * 6 + 0];
            ys[w * 6 + 1] = a.y  + b3[w * 6 + 1];
            ys[w * 6 + 2] = bb.x + b3[w * 6 + 2];
            ys[w * 6 + 3] = bb.y + b3[w * 6 + 3];
            ys[w * 6 + 4] = c.x  + b3[w * 6 + 4];
            ys[w * 6 + 5] = c.y  + b3[w * 6 + 5];
        }
    }
    __syncthreads();

    // ---- final linear on the mean vector ----
    if (t < 64) {
        float acc = lb[t];
#pragma unroll
        for (int k = 0; k < F3; k++) acc = fmaf(ys[k], lw[k * 64 + t], acc);
        out[(size_t)g * 64 + t] = acc;
    }
}

extern "C" void kernel_launch(void* const* d_in, const int* in_sizes, int n_in,
                              void* d_out, int out_size)
{
    const float* xs  = (const float*)d_in[0];
    const float* pe  = (const float*)d_in[1];
    const float* W1  = (const float*)d_in[2];
    const float* as1 = (const float*)d_in[3];
    const float* ad1 = (const float*)d_in[4];
    const float* b1  = (const float*)d_in[5];
    const float* W2  = (const float*)d_in[6];
    const float* as2 = (const float*)d_in[7];
    const float* ad2 = (const float*)d_in[8];
    const float* b2  = (const float*)d_in[9];
    const float* W3  = (const float*)d_in[10];
    const float* as3 = (const float*)d_in[11];
    const float* ad3 = (const float*)d_in[12];
    const float* b3  = (const float*)d_in[13];
    const float* lw  = (const float*)d_in[14];
    const float* lb  = (const float*)d_in[15];
    float* out = (float*)d_out;

    int B = in_sizes[1] / (32 * 15);
    int R = in_sizes[0] / (B * 32);
    int G = B * R;

    prep_kernel<<<33, 128>>>(W3, as3, ad3);
    gat_fused_kernel<<<G, THREADS>>>(xs, pe, W1, as1, ad1, b1,
                                     W2, as2, ad2, b2,
                                     b3, lw, lb, out, R);
}

// round 9
// speedup vs baseline: 1.3207x; 1.3207x over previous
#include <cuda_runtime.h>

// GAT over 16384 independent 32-node cliques, fully fused: one CTA per graph.
// Linear GEMMs run on tensor cores (mma.sync.m16n8k8 tf32) with fragment
// loads that deliver each operand byte exactly once (no smem broadcast
// redundancy). Attention (scores/softmax/aggregation) stays scalar fp32.

#define NCOL 32
#define HEADS 4
#define FH 128          // H * HID
#define FHP 132         // padded h row; (4*qr+qc) bank-exact for frag loads
#define F3 24           // H * OUT
#define XINP 20
#define THREADS 128
#define NEG_SLOPE 0.2f

typedef unsigned long long u64;

__device__ float W3p_g[FH * 32];   // W3 padded: [f][head*8+d], zeros at d=6,7

__device__ __forceinline__ float lrelu(float x) { return x > 0.f ? x : NEG_SLOPE * x; }

__device__ __forceinline__ u64 dup2(float x) {
    u64 r; asm("mov.b64 %0,{%1,%1};" : "=l"(r) : "f"(x)); return r;
}
__device__ __forceinline__ float2 unpack2(u64 v) {
    float2 r; asm("mov.b64 {%0,%1},%2;" : "=f"(r.x), "=f"(r.y) : "l"(v)); return r;
}
__device__ __forceinline__ void fma2(u64 &d, u64 a, u64 b) {
    asm("fma.rn.f32x2 %0,%1,%2,%0;" : "+l"(d) : "l"(a), "l"(b));
}
__device__ __forceinline__ void add2(u64 &d, u64 a) {
    asm("add.rn.f32x2 %0,%0,%1;" : "+l"(d) : "l"(a));
}
__device__ __forceinline__ unsigned cvt_tf32(float x) {
    unsigned r; asm("cvt.rna.tf32.f32 %0, %1;" : "=r"(r) : "f"(x)); return r;
}
// D = A(16x8,row) @ B(8x8,col-frag) + D, tf32 in, f32 accum
__device__ __forceinline__ void mma_t(float c[4], const unsigned a[4], const unsigned b[2]) {
    asm("mma.sync.aligned.m16n8k8.row.col.f32.tf32.tf32.f32 "
        "{%0,%1,%2,%3}, {%4,%5,%6,%7}, {%8,%9}, {%0,%1,%2,%3};"
        : "+f"(c[0]), "+f"(c[1]), "+f"(c[2]), "+f"(c[3])
        : "r"(a[0]), "r"(a[1]), "r"(a[2]), "r"(a[3]), "r"(b[0]), "r"(b[1]));
}

__global__ void pad_w3_kernel(const float* __restrict__ W3) {
    int idx = blockIdx.x * blockDim.x + threadIdx.x;   // 0..4095
    int f = idx >> 5, hp = idx & 31;
    int d = hp & 7, h = hp >> 3;
    W3p_g[idx] = (d < 6) ? W3[f * F3 + h * 6 + d] : 0.f;
}

// ---- attention for D=32 heads (layers 1 & 2), in-place on h ----
__device__ __forceinline__ void gat_attention32(
    float (*__restrict__ h)[FHP],
    const float* __restrict__ a_src, const float* __restrict__ a_dst,
    const float* __restrict__ bias,
    float* __restrict__ s_src, float* __restrict__ s_dst,
    float (*__restrict__ alpha)[NCOL], int t)
{
    const int head = t >> 5;
    const int lane = t & 31;
    const int c0 = head * 32;

    // phase 1: scores for node n = lane
    {
        const ulonglong2* hp = (const ulonglong2*)&h[lane][c0];
        const ulonglong2* ap = (const ulonglong2*)(a_src + c0);
        const ulonglong2* dp = (const ulonglong2*)(a_dst + c0);
        u64 ss2 = 0, sd2 = 0;
#pragma unroll
        for (int q = 0; q < 8; q++) {
            ulonglong2 hq = hp[q];
            ulonglong2 aq = ap[q];
            ulonglong2 dq = dp[q];
            fma2(ss2, hq.x, aq.x); fma2(ss2, hq.y, aq.y);
            fma2(sd2, hq.x, dq.x); fma2(sd2, hq.y, dq.y);
        }
        float2 s2 = unpack2(ss2);
        float2 d2 = unpack2(sd2);
        s_src[head * NCOL + lane] = s2.x + s2.y;
        s_dst[head * NCOL + lane] = d2.x + d2.y;
    }
    __syncwarp();

    // phase 2: softmax; store rotated, rinv-scaled alpha
    {
        const float sdst = s_dst[head * NCOL + lane];
        float e[NCOL];
        float m = -1e30f;
#pragma unroll
        for (int q = 0; q < 8; q++) {
            float4 sv = *(const float4*)&s_src[head * NCOL + 4 * q];
            e[4*q+0] = lrelu(sdst + sv.x);
            e[4*q+1] = lrelu(sdst + sv.y);
            e[4*q+2] = lrelu(sdst + sv.z);
            e[4*q+3] = lrelu(sdst + sv.w);
        }
#pragma unroll
        for (int j = 0; j < NCOL; j++) m = fmaxf(m, e[j]);
        float sum = 0.f;
#pragma unroll
        for (int j = 0; j < NCOL; j++) {
            e[j] = __expf(e[j] - m);
            sum += e[j];
        }
        const float rinv = 1.f / sum;
        const int rot = lane >> 2;
#pragma unroll
        for (int q = 0; q < 8; q++) {
            int col = ((q + rot) & 7) * 4;
            float4 v;
            v.x = e[4*q+0] * rinv;
            v.y = e[4*q+1] * rinv;
            v.z = e[4*q+2] * rinv;
            v.w = e[4*q+3] * rinv;
            *(float4*)&alpha[lane][col] = v;
        }
    }
    __syncwarp();

    // phase 3: out(32x32) = alpha @ h_head (channel-packed fp32x2)
    const int ng = lane >> 2;
    const int cg = lane & 3;
    const int cb = c0 + 8 * cg;
    u64 acc2[4][4];
#pragma unroll
    for (int i = 0; i < 4; i++)
#pragma unroll
        for (int p = 0; p < 4; p++) acc2[i][p] = 0;

#pragma unroll
    for (int j0 = 0; j0 < NCOL; j0 += 4) {
        float4 av[4];
        const int colb = (((j0 >> 2) + ng) & 7) * 4;
#pragma unroll
        for (int i = 0; i < 4; i++)
            av[i] = *(const float4*)&alpha[4 * ng + i][colb];
#pragma unroll
        for (int jj = 0; jj < 4; jj++) {
            ulonglong2 h0 = *(const ulonglong2*)&h[j0 + jj][cb];
            ulonglong2 h1 = *(const ulonglong2*)&h[j0 + jj][cb + 4];
#pragma unroll
            for (int i = 0; i < 4; i++) {
                u64 a = dup2(((const float*)&av[i])[jj]);
                fma2(acc2[i][0], a, h0.x);
                fma2(acc2[i][1], a, h0.y);
                fma2(acc2[i][2], a, h1.x);
                fma2(acc2[i][3], a, h1.y);
            }
        }
    }
    __syncthreads();   // everyone done reading h before in-place overwrite

    ulonglong2 b01 = *(const ulonglong2*)&bias[cb];
    ulonglong2 b23 = *(const ulonglong2*)&bias[cb + 4];
#pragma unroll
    for (int i = 0; i < 4; i++) {
        int row = 4 * ng + i;
        u64 o0 = acc2[i][0], o1 = acc2[i][1], o2 = acc2[i][2], o3 = acc2[i][3];
        add2(o0, b01.x); add2(o1, b01.y); add2(o2, b23.x); add2(o3, b23.y);
        ulonglong2 s0; s0.x = o0; s0.y = o1;
        ulonglong2 s1; s1.x = o2; s1.y = o3;
        *(ulonglong2*)&h[row][cb]     = s0;
        *(ulonglong2*)&h[row][cb + 4] = s1;
    }
    __syncthreads();
}

// ---- attention for D=6 (layer 3), padded layout: head d at col head*8+d ----
__device__ __forceinline__ void gat_attention6(
    float (*__restrict__ h)[FHP],
    const float* __restrict__ a_src, const float* __restrict__ a_dst,
    const float* __restrict__ bias,
    float* __restrict__ s_src, float* __restrict__ s_dst, int t)
{
    const int head = t >> 5;
    const int n = t & 31;
    const int cp = head * 8;
    const int c0 = head * 6;

    float ss, sd;
    {
        float4 hv0 = *(const float4*)&h[n][cp];
        float2 hv1 = *(const float2*)&h[n][cp + 4];
        ss = fmaf(hv0.x, a_src[c0+0], fmaf(hv0.y, a_src[c0+1], fmaf(hv0.z, a_src[c0+2],
             fmaf(hv0.w, a_src[c0+3], fmaf(hv1.x, a_src[c0+4], hv1.y * a_src[c0+5])))));
        sd = fmaf(hv0.x, a_dst[c0+0], fmaf(hv0.y, a_dst[c0+1], fmaf(hv0.z, a_dst[c0+2],
             fmaf(hv0.w, a_dst[c0+3], fmaf(hv1.x, a_dst[c0+4], hv1.y * a_dst[c0+5])))));
    }
    s_src[head * NCOL + n] = ss;
    s_dst[head * NCOL + n] = sd;
    __syncwarp();

    const float sdst = s_dst[head * NCOL + n];
    float e[NCOL];
    float m = -1e30f;
#pragma unroll
    for (int q = 0; q < 8; q++) {
        float4 sv = *(const float4*)&s_src[head * NCOL + 4 * q];
        e[4*q+0] = lrelu(sdst + sv.x);
        e[4*q+1] = lrelu(sdst + sv.y);
        e[4*q+2] = lrelu(sdst + sv.z);
        e[4*q+3] = lrelu(sdst + sv.w);
    }
#pragma unroll
    for (int j = 0; j < NCOL; j++) m = fmaxf(m, e[j]);
    float sum = 0.f;
#pragma unroll
    for (int j = 0; j < NCOL; j++) {
        e[j] = __expf(e[j] - m);
        sum += e[j];
    }
    const float rinv = 1.f / sum;

    u64 acc2[3] = {0, 0, 0};
#pragma unroll
    for (int j = 0; j < NCOL; j++) {
        u64 a = dup2(e[j]);
        ulonglong2 hh = *(const ulonglong2*)&h[j][cp];
        u64 h2 = *(const u64*)&h[j][cp + 4];
        fma2(acc2[0], a, hh.x);
        fma2(acc2[1], a, hh.y);
        fma2(acc2[2], a, h2);
    }
    float2 p0 = unpack2(acc2[0]);
    float2 p1 = unpack2(acc2[1]);
    float2 p2 = unpack2(acc2[2]);
    __syncthreads();
    h[n][cp + 0] = fmaf(p0.x, rinv, bias[c0 + 0]);
    h[n][cp + 1] = fmaf(p0.y, rinv, bias[c0 + 1]);
    h[n][cp + 2] = fmaf(p1.x, rinv, bias[c0 + 2]);
    h[n][cp + 3] = fmaf(p1.y, rinv, bias[c0 + 3]);
    h[n][cp + 4] = fmaf(p2.x, rinv, bias[c0 + 4]);
    h[n][cp + 5] = fmaf(p2.y, rinv, bias[c0 + 5]);
    __syncthreads();
}

__global__ void __launch_bounds__(THREADS, 6) gat_fused_kernel(
    const float* __restrict__ xs,
    const float* __restrict__ pe,
    const float* __restrict__ W1,
    const float* __restrict__ as1, const float* __restrict__ ad1,
    const float* __restrict__ b1,
    const float* __restrict__ W2,
    const float* __restrict__ as2, const float* __restrict__ ad2,
    const float* __restrict__ b2,
    const float* __restrict__ as3, const float* __restrict__ ad3,
    const float* __restrict__ b3,
    const float* __restrict__ lw,
    const float* __restrict__ lb,
    float* __restrict__ out,
    int R)
{
    __shared__ float hs[NCOL][FHP];
    __shared__ float alphas[HEADS][NCOL][NCOL];
    __shared__ float s_src[HEADS * NCOL];
    __shared__ float s_dst[HEADS * NCOL];
    __shared__ float xin[NCOL][XINP];
    __shared__ float cs[F3];

    const int g = blockIdx.x;
    const int b = g / R;
    const int r = g - b * R;
    const int t = threadIdx.x;
    const int lane = t & 31;
    const int w = t >> 5;
    const int qr = lane >> 2;     // fragment row group 0..7
    const int qc = lane & 3;      // fragment col-in-quad 0..3

    // ---- build input features ----
    for (int idx = t; idx < NCOL * 16; idx += THREADS) {
        int n = idx >> 4, f = idx & 15;
        float v;
        if (f == 0) v = xs[(size_t)(b * R + r) * NCOL + n];
        else        v = pe[(b * NCOL + n) * 15 + (f - 1)];
        xin[n][f] = v;
    }
    __syncthreads();

    // ---- layer 1 GEMM (tensor core): warp w -> out cols 32w..32w+31 ----
    {
        const int cwb = 32 * w;
        float C[2][4][4];
#pragma unroll
        for (int mb = 0; mb < 2; mb++)
#pragma unroll
            for (int nt = 0; nt < 4; nt++)
#pragma unroll
                for (int i = 0; i < 4; i++) C[mb][nt][i] = 0.f;

#pragma unroll
        for (int kt = 0; kt < 2; kt++) {
            const int k0 = kt * 8;
            unsigned a[2][4];
#pragma unroll
            for (int mb = 0; mb < 2; mb++) {
                const int r0 = mb * 16 + qr;
                a[mb][0] = cvt_tf32(xin[r0][k0 + qc]);
                a[mb][1] = cvt_tf32(xin[r0 + 8][k0 + qc]);
                a[mb][2] = cvt_tf32(xin[r0][k0 + qc + 4]);
                a[mb][3] = cvt_tf32(xin[r0 + 8][k0 + qc + 4]);
            }
#pragma unroll
            for (int nt = 0; nt < 4; nt++) {
                unsigned bf[2];
                const float* wp = W1 + cwb + nt * 8 + qr;
                bf[0] = cvt_tf32(wp[(k0 + qc) * FH]);
                bf[1] = cvt_tf32(wp[(k0 + qc + 4) * FH]);
#pragma unroll
                for (int mb = 0; mb < 2; mb++) mma_t(C[mb][nt], a[mb], bf);
            }
        }
#pragma unroll
        for (int mb = 0; mb < 2; mb++)
#pragma unroll
            for (int nt = 0; nt < 4; nt++) {
                const int c = cwb + nt * 8 + 2 * qc;
                *(float2*)&hs[mb * 16 + qr][c]     = make_float2(C[mb][nt][0], C[mb][nt][1]);
                *(float2*)&hs[mb * 16 + qr + 8][c] = make_float2(C[mb][nt][2], C[mb][nt][3]);
            }
    }
    __syncthreads();
    gat_attention32(hs, as1, ad1, b1, s_src, s_dst, alphas[w], t);

    // ---- layer 2 GEMM (tensor core): warp w -> out cols 32w..32w+31 ----
    {
        const int cwb = 32 * w;
        float C[2][4][4];
#pragma unroll
        for (int mb = 0; mb < 2; mb++)
#pragma unroll
            for (int nt = 0; nt < 4; nt++)
#pragma unroll
                for (int i = 0; i < 4; i++) C[mb][nt][i] = 0.f;

#pragma unroll 4
        for (int kt = 0; kt < 16; kt++) {
            const int k0 = kt * 8;
            unsigned a[2][4];
#pragma unroll
            for (int mb = 0; mb < 2; mb++) {
                const int r0 = mb * 16 + qr;
                a[mb][0] = cvt_tf32(hs[r0][k0 + qc]);
                a[mb][1] = cvt_tf32(hs[r0 + 8][k0 + qc]);
                a[mb][2] = cvt_tf32(hs[r0][k0 + qc + 4]);
                a[mb][3] = cvt_tf32(hs[r0 + 8][k0 + qc + 4]);
            }
#pragma unroll
            for (int nt = 0; nt < 4; nt++) {
                unsigned bf[2];
                const float* wp = W2 + cwb + nt * 8 + qr;
                bf[0] = cvt_tf32(wp[(k0 + qc) * FH]);
                bf[1] = cvt_tf32(wp[(k0 + qc + 4) * FH]);
#pragma unroll
                for (int mb = 0; mb < 2; mb++) mma_t(C[mb][nt], a[mb], bf);
            }
        }
        __syncthreads();   // all warps done reading hs before overwrite
#pragma unroll
        for (int mb = 0; mb < 2; mb++)
#pragma unroll
            for (int nt = 0; nt < 4; nt++) {
                const int c = cwb + nt * 8 + 2 * qc;
                *(float2*)&hs[mb * 16 + qr][c]     = make_float2(C[mb][nt][0], C[mb][nt][1]);
                *(float2*)&hs[mb * 16 + qr + 8][c] = make_float2(C[mb][nt][2], C[mb][nt][3]);
            }
    }
    __syncthreads();
    gat_attention32(hs, as2, ad2, b2, s_src, s_dst, alphas[w], t);

    // ---- layer 3 GEMM (tensor core): warp w -> padded cols 8w..8w+7, all rows ----
    {
        float C[2][4];
#pragma unroll
        for (int mb = 0; mb < 2; mb++)
#pragma unroll
            for (int i = 0; i < 4; i++) C[mb][i] = 0.f;

#pragma unroll 4
        for (int kt = 0; kt < 16; kt++) {
            const int k0 = kt * 8;
            unsigned a[2][4];
#pragma unroll
            for (int mb = 0; mb < 2; mb++) {
                const int r0 = mb * 16 + qr;
                a[mb][0] = cvt_tf32(hs[r0][k0 + qc]);
                a[mb][1] = cvt_tf32(hs[r0 + 8][k0 + qc]);
                a[mb][2] = cvt_tf32(hs[r0][k0 + qc + 4]);
                a[mb][3] = cvt_tf32(hs[r0 + 8][k0 + qc + 4]);
            }
            unsigned bf[2];
            const float* wp = W3p_g + 8 * w + qr;
            bf[0] = cvt_tf32(wp[(k0 + qc) * 32]);
            bf[1] = cvt_tf32(wp[(k0 + qc + 4) * 32]);
#pragma unroll
            for (int mb = 0; mb < 2; mb++) mma_t(C[mb], a[mb], bf);
        }
        __syncthreads();   // all warps done reading hs before writing cols 0..31
#pragma unroll
        for (int mb = 0; mb < 2; mb++) {
            const int c = 8 * w + 2 * qc;
            *(float2*)&hs[mb * 16 + qr][c]     = make_float2(C[mb][0], C[mb][1]);
            *(float2*)&hs[mb * 16 + qr + 8][c] = make_float2(C[mb][2], C[mb][3]);
        }
    }
    __syncthreads();
    gat_attention6(hs, as3, ad3, b3, s_src, s_dst, t);

    // ---- final: mean over nodes commutes with linear (padded layout) ----
    if (t < F3) {
        int head = t / 6, d = t - head * 6;
        float s = 0.f;
#pragma unroll
        for (int n = 0; n < NCOL; n++) s += hs[n][head * 8 + d];
        cs[t] = s * (1.f / 32.f);
    }
    __syncthreads();
    if (t < 64) {
        float acc = lb[t];
#pragma unroll
        for (int k = 0; k < F3; k++) acc = fmaf(cs[k], lw[k * 64 + t], acc);
        out[(size_t)g * 64 + t] = acc;
    }
}

extern "C" void kernel_launch(void* const* d_in, const int* in_sizes, int n_in,
                              void* d_out, int out_size)
{
    const float* xs  = (const float*)d_in[0];
    const float* pe  = (const float*)d_in[1];
    const float* W1  = (const float*)d_in[2];
    const float* as1 = (const float*)d_in[3];
    const float* ad1 = (const float*)d_in[4];
    const float* b1  = (const float*)d_in[5];
    const float* W2  = (const float*)d_in[6];
    const float* as2 = (const float*)d_in[7];
    const float* ad2 = (const float*)d_in[8];
    const float* b2  = (const float*)d_in[9];
    const float* W3  = (const float*)d_in[10];
    const float* as3 = (const float*)d_in[11];
    const float* ad3 = (const float*)d_in[12];
    const float* b3  = (const float*)d_in[13];
    const float* lw  = (const float*)d_in[14];
    const float* lb  = (const float*)d_in[15];
    float* out = (float*)d_out;

    int B = in_sizes[1] / (32 * 15);
    int R = in_sizes[0] / (B * 32);
    int G = B * R;

    pad_w3_kernel<<<32, 128>>>(W3);
    gat_fused_kernel<<<G, THREADS>>>(xs, pe, W1, as1, ad1, b1,
                                     W2, as2, ad2, b2,
                                     as3, ad3, b3,
                                     lw, lb, out, R);
}

// round 10
// speedup vs baseline: 1.7390x; 1.3167x over previous
#include <cuda_runtime.h>

// GAT over 16384 independent 32-node cliques, fully fused: one CTA per graph.
// ALL matrix products (3 linear GEMMs + all 3 attention aggregations) run on
// tensor cores (mma.sync.m16n8k8 tf32, fp32 accum). Scores/softmax stay fp32.
// alpha lives in smem at stride 36 (bank = 4*row+col -> conflict-free frags).

#define NCOL 32
#define HEADS 4
#define FH 128
#define FHP 132         // hs row stride: 4*row+col bank pattern for frag loads
#define F3 24
#define XINP 20
#define ASTR 36         // alpha row stride
#define THREADS 128
#define NEG_SLOPE 0.2f

typedef unsigned long long u64;

__device__ float W1r_g[16 * FH];    // tf32-rounded weights
__device__ float W2r_g[FH * FH];
__device__ float W3r_g[FH * 32];    // padded [f][head*8+d], zeros at d=6,7
__device__ float as3p_g[32];        // padded fp32
__device__ float ad3p_g[32];

__device__ __forceinline__ float lrelu(float x) { return x > 0.f ? x : NEG_SLOPE * x; }

__device__ __forceinline__ u64 pack2(float a, float b) {
    u64 r; asm("mov.b64 %0,{%1,%2};" : "=l"(r) : "f"(a), "f"(b)); return r;
}
__device__ __forceinline__ float2 unpack2(u64 v) {
    float2 r; asm("mov.b64 {%0,%1},%2;" : "=f"(r.x), "=f"(r.y) : "l"(v)); return r;
}
__device__ __forceinline__ void fma2(u64 &d, u64 a, u64 b) {
    asm("fma.rn.f32x2 %0,%1,%2,%0;" : "+l"(d) : "l"(a), "l"(b));
}
__device__ __forceinline__ void add2(u64 &d, u64 a) {
    asm("add.rn.f32x2 %0,%0,%1;" : "+l"(d) : "l"(a));
}
__device__ __forceinline__ u64 shfl_xor_u64(u64 v, int m) {
    unsigned lo, hi;
    asm("mov.b64 {%0,%1},%2;" : "=r"(lo), "=r"(hi) : "l"(v));
    lo = __shfl_xor_sync(0xffffffffu, lo, m);
    hi = __shfl_xor_sync(0xffffffffu, hi, m);
    u64 r; asm("mov.b64 %0,{%1,%2};" : "=l"(r) : "r"(lo), "r"(hi));
    return r;
}
__device__ __forceinline__ unsigned cvt_tf32(float x) {
    unsigned r; asm("cvt.rna.tf32.f32 %0, %1;" : "=r"(r) : "f"(x)); return r;
}
__device__ __forceinline__ float tf32f(float x) { return __uint_as_float(cvt_tf32(x)); }

__device__ __forceinline__ void mma_t(float c[4], const unsigned a[4], const unsigned b[2]) {
    asm("mma.sync.aligned.m16n8k8.row.col.f32.tf32.tf32.f32 "
        "{%0,%1,%2,%3}, {%4,%5,%6,%7}, {%8,%9}, {%0,%1,%2,%3};"
        : "+f"(c[0]), "+f"(c[1]), "+f"(c[2]), "+f"(c[3])
        : "r"(a[0]), "r"(a[1]), "r"(a[2]), "r"(a[3]), "r"(b[0]), "r"(b[1]));
}

__global__ void prep_kernel(const float* __restrict__ W1, const float* __restrict__ W2,
                            const float* __restrict__ W3, const float* __restrict__ as3,
                            const float* __restrict__ ad3) {
    int idx = blockIdx.x * blockDim.x + threadIdx.x;
    if (idx < 2048) {
        W1r_g[idx] = tf32f(W1[idx]);
    } else if (idx < 18432) {
        int i = idx - 2048;
        W2r_g[i] = tf32f(W2[i]);
    } else if (idx < 22528) {
        int i = idx - 18432;
        int f = i >> 5, hp = i & 31, d = hp & 7, h = hp >> 3;
        W3r_g[i] = (d < 6) ? tf32f(W3[f * F3 + h * 6 + d]) : 0.f;
    } else if (idx < 22560) {
        int i = idx - 22528, h = i >> 3, d = i & 7;
        as3p_g[i] = (d < 6) ? as3[h * 6 + d] : 0.f;
    } else if (idx < 22592) {
        int i = idx - 22560, h = i >> 3, d = i & 7;
        ad3p_g[i] = (d < 6) ? ad3[h * 6 + d] : 0.f;
    }
}

// softmax (phase 2): e -> alpha row (tf32), given sdst and s_src block.
__device__ __forceinline__ void softmax_to_alpha(
    const float* __restrict__ s_src_blk, float sdst,
    float (*__restrict__ alpha)[ASTR], int lane)
{
    float e[NCOL];
    float m = -1e30f;
#pragma unroll
    for (int q = 0; q < 8; q++) {
        float4 sv = *(const float4*)&s_src_blk[4 * q];
        e[4*q+0] = lrelu(sdst + sv.x);
        e[4*q+1] = lrelu(sdst + sv.y);
        e[4*q+2] = lrelu(sdst + sv.z);
        e[4*q+3] = lrelu(sdst + sv.w);
    }
#pragma unroll
    for (int j = 0; j < NCOL; j++) m = fmaxf(m, e[j]);
    float sum = 0.f;
#pragma unroll
    for (int j = 0; j < NCOL; j++) {
        e[j] = __expf(e[j] - m);
        sum += e[j];
    }
    const float rinv = 1.f / sum;
#pragma unroll
    for (int q = 0; q < 8; q++) {
        float4 v;
        v.x = tf32f(e[4*q+0] * rinv);
        v.y = tf32f(e[4*q+1] * rinv);
        v.z = tf32f(e[4*q+2] * rinv);
        v.w = tf32f(e[4*q+3] * rinv);
        *(float4*)&alpha[lane][4 * q] = v;
    }
}

// Full attention for D=32 head (layers 1 & 2): scores + softmax + MMA agg, in-place.
__device__ __forceinline__ void attn32(
    float (*__restrict__ hs)[FHP],
    float (*__restrict__ alpha)[ASTR],
    const float* __restrict__ a_src, const float* __restrict__ a_dst,
    const float* __restrict__ bias,
    float* __restrict__ s_src, float* __restrict__ s_dst,
    int w, int lane, int qr, int qc)
{
    const int c0 = 32 * w;
    __syncwarp();   // order prior epilogue stores (cross-lane, same warp)

    // phase 1: fp32 scores for node n = lane
    {
        const ulonglong2* hp = (const ulonglong2*)&hs[lane][c0];
        const ulonglong2* ap = (const ulonglong2*)(a_src + c0);
        const ulonglong2* dp = (const ulonglong2*)(a_dst + c0);
        u64 ss2 = 0, sd2 = 0;
#pragma unroll
        for (int q = 0; q < 8; q++) {
            ulonglong2 hq = hp[q];
            ulonglong2 aq = ap[q];
            ulonglong2 dq = dp[q];
            fma2(ss2, hq.x, aq.x); fma2(ss2, hq.y, aq.y);
            fma2(sd2, hq.x, dq.x); fma2(sd2, hq.y, dq.y);
        }
        float2 s2 = unpack2(ss2);
        float2 d2 = unpack2(sd2);
        s_src[w * NCOL + lane] = s2.x + s2.y;
        s_dst[w * NCOL + lane] = d2.x + d2.y;
    }
    __syncwarp();

    // phase 2
    softmax_to_alpha(&s_src[w * NCOL], s_dst[w * NCOL + lane], alpha, lane);
    __syncwarp();

    // phase 3: MMA  out(32x32) = alpha @ h_head, in-place (warp-local columns)
    float C[2][4][4];
#pragma unroll
    for (int mb = 0; mb < 2; mb++)
#pragma unroll
        for (int nt = 0; nt < 4; nt++)
#pragma unroll
            for (int i = 0; i < 4; i++) C[mb][nt][i] = 0.f;

#pragma unroll
    for (int kt = 0; kt < 4; kt++) {
        const int k0 = 8 * kt;
        unsigned a[2][4];
#pragma unroll
        for (int mb = 0; mb < 2; mb++) {
            const int r0 = 16 * mb + qr;
            a[mb][0] = __float_as_uint(alpha[r0][k0 + qc]);
            a[mb][1] = __float_as_uint(alpha[r0 + 8][k0 + qc]);
            a[mb][2] = __float_as_uint(alpha[r0][k0 + qc + 4]);
            a[mb][3] = __float_as_uint(alpha[r0 + 8][k0 + qc + 4]);
        }
#pragma unroll
        for (int nt = 0; nt < 4; nt++) {
            unsigned bf[2];
            bf[0] = cvt_tf32(hs[k0 + qc][c0 + 8 * nt + qr]);
            bf[1] = cvt_tf32(hs[k0 + qc + 4][c0 + 8 * nt + qr]);
#pragma unroll
            for (int mb = 0; mb < 2; mb++) mma_t(C[mb][nt], a[mb], bf);
        }
    }
    // epilogue: + bias, in-place store (all B loads precede stores in program order)
#pragma unroll
    for (int nt = 0; nt < 4; nt++) {
        const int c = c0 + 8 * nt + 2 * qc;
        float b0 = bias[c], b1 = bias[c + 1];
#pragma unroll
        for (int mb = 0; mb < 2; mb++) {
            *(float2*)&hs[16 * mb + qr][c]     = make_float2(C[mb][nt][0] + b0, C[mb][nt][1] + b1);
            *(float2*)&hs[16 * mb + qr + 8][c] = make_float2(C[mb][nt][2] + b0, C[mb][nt][3] + b1);
        }
    }
}

__global__ void __launch_bounds__(THREADS, 6) gat_fused_kernel(
    const float* __restrict__ xs,
    const float* __restrict__ pe,
    const float* __restrict__ as1, const float* __restrict__ ad1,
    const float* __restrict__ b1,
    const float* __restrict__ as2, const float* __restrict__ ad2,
    const float* __restrict__ b2,
    const float* __restrict__ b3,
    const float* __restrict__ lw,
    const float* __restrict__ lb,
    float* __restrict__ out,
    int R)
{
    __shared__ float hs[NCOL][FHP];                    // 16.9 KB
    __shared__ float alphas[HEADS][NCOL][ASTR];        // 18.4 KB
    __shared__ float s_src[HEADS * NCOL];
    __shared__ float s_dst[HEADS * NCOL];
    __shared__ float cs[F3];

    // xin overlays alphas (xin dead after GEMM1; alphas first written in attn1)
    float (*xin)[XINP] = (float(*)[XINP]) & alphas[0][0][0];

    const int g = blockIdx.x;
    const int b = g / R;
    const int r = g - b * R;
    const int t = threadIdx.x;
    const int lane = t & 31;
    const int w = t >> 5;
    const int qr = lane >> 2;
    const int qc = lane & 3;
    const int cwb = 32 * w;

    // ---- build input features (pre-rounded to tf32; only GEMM1 reads xin) ----
    for (int idx = t; idx < NCOL * 16; idx += THREADS) {
        int n = idx >> 4, f = idx & 15;
        float v;
        if (f == 0) v = xs[(size_t)(b * R + r) * NCOL + n];
        else        v = pe[(b * NCOL + n) * 15 + (f - 1)];
        xin[n][f] = tf32f(v);
    }
    __syncthreads();

    // ---- layer 1 GEMM (tensor): warp w -> out cols 32w..32w+31 ----
    {
        float C[2][4][4];
#pragma unroll
        for (int mb = 0; mb < 2; mb++)
#pragma unroll
            for (int nt = 0; nt < 4; nt++)
#pragma unroll
                for (int i = 0; i < 4; i++) C[mb][nt][i] = 0.f;

#pragma unroll
        for (int kt = 0; kt < 2; kt++) {
            const int k0 = 8 * kt;
            unsigned a[2][4];
#pragma unroll
            for (int mb = 0; mb < 2; mb++) {
                const int r0 = 16 * mb + qr;
                a[mb][0] = __float_as_uint(xin[r0][k0 + qc]);
                a[mb][1] = __float_as_uint(xin[r0 + 8][k0 + qc]);
                a[mb][2] = __float_as_uint(xin[r0][k0 + qc + 4]);
                a[mb][3] = __float_as_uint(xin[r0 + 8][k0 + qc + 4]);
            }
#pragma unroll
            for (int nt = 0; nt < 4; nt++) {
                unsigned bf[2];
                const float* wp = W1r_g + cwb + nt * 8 + qr;
                bf[0] = __float_as_uint(wp[(k0 + qc) * FH]);
                bf[1] = __float_as_uint(wp[(k0 + qc + 4) * FH]);
#pragma unroll
                for (int mb = 0; mb < 2; mb++) mma_t(C[mb][nt], a[mb], bf);
            }
        }
#pragma unroll
        for (int mb = 0; mb < 2; mb++)
#pragma unroll
            for (int nt = 0; nt < 4; nt++) {
                const int c = cwb + nt * 8 + 2 * qc;
                *(float2*)&hs[16 * mb + qr][c]     = make_float2(C[mb][nt][0], C[mb][nt][1]);
                *(float2*)&hs[16 * mb + qr + 8][c] = make_float2(C[mb][nt][2], C[mb][nt][3]);
            }
    }
    __syncthreads();   // xin reads done -> alphas writable; hs visible

    attn32(hs, alphas[w], as1, ad1, b1, s_src, s_dst, w, lane, qr, qc);
    __syncthreads();   // GEMM2 reads all columns

    // ---- layer 2 GEMM (tensor): warp w -> out cols 32w..32w+31 ----
    {
        float C[2][4][4];
#pragma unroll
        for (int mb = 0; mb < 2; mb++)
#pragma unroll
            for (int nt = 0; nt < 4; nt++)
#pragma unroll
                for (int i = 0; i < 4; i++) C[mb][nt][i] = 0.f;

#pragma unroll 4
        for (int kt = 0; kt < 16; kt++) {
            const int k0 = 8 * kt;
            unsigned a[2][4];
#pragma unroll
            for (int mb = 0; mb < 2; mb++) {
                const int r0 = 16 * mb + qr;
                a[mb][0] = cvt_tf32(hs[r0][k0 + qc]);
                a[mb][1] = cvt_tf32(hs[r0 + 8][k0 + qc]);
                a[mb][2] = cvt_tf32(hs[r0][k0 + qc + 4]);
                a[mb][3] = cvt_tf32(hs[r0 + 8][k0 + qc + 4]);
            }
#pragma unroll
            for (int nt = 0; nt < 4; nt++) {
                unsigned bf[2];
                const float* wp = W2r_g + cwb + nt * 8 + qr;
                bf[0] = __float_as_uint(wp[(k0 + qc) * FH]);
                bf[1] = __float_as_uint(wp[(k0 + qc + 4) * FH]);
#pragma unroll
                for (int mb = 0; mb < 2; mb++) mma_t(C[mb][nt], a[mb], bf);
            }
        }
        __syncthreads();   // all warps done reading hs before overwrite
#pragma unroll
        for (int mb = 0; mb < 2; mb++)
#pragma unroll
            for (int nt = 0; nt < 4; nt++) {
                const int c = cwb + nt * 8 + 2 * qc;
                *(float2*)&hs[16 * mb + qr][c]     = make_float2(C[mb][nt][0], C[mb][nt][1]);
                *(float2*)&hs[16 * mb + qr + 8][c] = make_float2(C[mb][nt][2], C[mb][nt][3]);
            }
    }
    attn32(hs, alphas[w], as2, ad2, b2, s_src, s_dst, w, lane, qr, qc);
    __syncthreads();   // GEMM3 reads all columns

    // ---- layer 3 GEMM (tensor): warp w -> padded cols 8w..8w+7 ----
    {
        float C[2][4];
#pragma unroll
        for (int mb = 0; mb < 2; mb++)
#pragma unroll
            for (int i = 0; i < 4; i++) C[mb][i] = 0.f;

#pragma unroll 4
        for (int kt = 0; kt < 16; kt++) {
            const int k0 = 8 * kt;
            unsigned a[2][4];
#pragma unroll
            for (int mb = 0; mb < 2; mb++) {
                const int r0 = 16 * mb + qr;
                a[mb][0] = cvt_tf32(hs[r0][k0 + qc]);
                a[mb][1] = cvt_tf32(hs[r0 + 8][k0 + qc]);
                a[mb][2] = cvt_tf32(hs[r0][k0 + qc + 4]);
                a[mb][3] = cvt_tf32(hs[r0 + 8][k0 + qc + 4]);
            }
            unsigned bf[2];
            const float* wp = W3r_g + 8 * w + qr;
            bf[0] = __float_as_uint(wp[(k0 + qc) * 32]);
            bf[1] = __float_as_uint(wp[(k0 + qc + 4) * 32]);
#pragma unroll
            for (int mb = 0; mb < 2; mb++) mma_t(C[mb], a[mb], bf);
        }
        __syncthreads();   // all warps done reading hs before writing cols 0..31
#pragma unroll
        for (int mb = 0; mb < 2; mb++) {
            const int c = 8 * w + 2 * qc;
            *(float2*)&hs[16 * mb + qr][c]     = make_float2(C[mb][0], C[mb][1]);
            *(float2*)&hs[16 * mb + qr + 8][c] = make_float2(C[mb][2], C[mb][3]);
        }
    }
    __syncwarp();   // order cross-lane stores within warp

    // ---- layer-3 attention: scores + softmax + MMA (NT=1) + register tail ----
    {
        const int cp = 8 * w;

        // phase 1: scores (padded cols; d=6,7 are exact zeros)
        {
            ulonglong2 hq = *(const ulonglong2*)&hs[lane][cp];
            ulonglong2 aq = *(const ulonglong2*)(as3p_g + cp);
            ulonglong2 dq = *(const ulonglong2*)(ad3p_g + cp);
            u64 ss2 = 0, sd2 = 0;
            fma2(ss2, hq.x, aq.x); fma2(ss2, hq.y, aq.y);
            fma2(sd2, hq.x, dq.x); fma2(sd2, hq.y, dq.y);
            float2 s2 = unpack2(ss2);
            float2 d2 = unpack2(sd2);
            s_src[w * NCOL + lane] = s2.x + s2.y;
            s_dst[w * NCOL + lane] = d2.x + d2.y;
        }
        __syncwarp();

        softmax_to_alpha(&s_src[w * NCOL], s_dst[w * NCOL + lane], alphas[w], lane);
        __syncwarp();

        // MMA: h3post = alpha @ h3 (NT=1); keep C in registers (no store)
        float C[2][4];
#pragma unroll
        for (int mb = 0; mb < 2; mb++)
#pragma unroll
            for (int i = 0; i < 4; i++) C[mb][i] = 0.f;

#pragma unroll
        for (int kt = 0; kt < 4; kt++) {
            const int k0 = 8 * kt;
            unsigned a[2][4];
#pragma unroll
            for (int mb = 0; mb < 2; mb++) {
                const int r0 = 16 * mb + qr;
                a[mb][0] = __float_as_uint(alphas[w][r0][k0 + qc]);
                a[mb][1] = __float_as_uint(alphas[w][r0 + 8][k0 + qc]);
                a[mb][2] = __float_as_uint(alphas[w][r0][k0 + qc + 4]);
                a[mb][3] = __float_as_uint(alphas[w][r0 + 8][k0 + qc + 4]);
            }
            unsigned bf[2];
            bf[0] = cvt_tf32(hs[k0 + qc][cp + qr]);
            bf[1] = cvt_tf32(hs[k0 + qc + 4][cp + qr]);
#pragma unroll
            for (int mb = 0; mb < 2; mb++) mma_t(C[mb], a[mb], bf);
        }

        // tail: node-mean of h3post directly from C fragments.
        // lane holds rows {qr, qr+8, qr+16, qr+24} of cols cp+2qc, cp+2qc+1.
        float se = C[0][0] + C[0][2] + C[1][0] + C[1][2];   // col cp+2qc
        float so = C[0][1] + C[0][3] + C[1][1] + C[1][3];   // col cp+2qc+1
        u64 p = pack2(se, so);
        add2(p, shfl_xor_u64(p, 4));
        add2(p, shfl_xor_u64(p, 8));
        add2(p, shfl_xor_u64(p, 16));
        if (qr == 0 && qc < 3) {
            float2 pv = unpack2(p);
            cs[w * 6 + 2 * qc]     = pv.x * (1.f / 32.f) + b3[w * 6 + 2 * qc];
            cs[w * 6 + 2 * qc + 1] = pv.y * (1.f / 32.f) + b3[w * 6 + 2 * qc + 1];
        }
    }
    __syncthreads();

    // ---- final linear on the mean vector ----
    if (t < 64) {
        float acc = lb[t];
#pragma unroll
        for (int k = 0; k < F3; k++) acc = fmaf(cs[k], lw[k * 64 + t], acc);
        out[(size_t)g * 64 + t] = acc;
    }
}

extern "C" void kernel_launch(void* const* d_in, const int* in_sizes, int n_in,
                              void* d_out, int out_size)
{
    const float* xs  = (const float*)d_in[0];
    const float* pe  = (const float*)d_in[1];
    const float* W1  = (const float*)d_in[2];
    const float* as1 = (const float*)d_in[3];
    const float* ad1 = (const float*)d_in[4];
    const float* b1  = (const float*)d_in[5];
    const float* W2  = (const float*)d_in[6];
    const float* as2 = (const float*)d_in[7];
    const float* ad2 = (const float*)d_in[8];
    const float* b2  = (const float*)d_in[9];
    const float* W3  = (const float*)d_in[10];
    const float* as3 = (const float*)d_in[11];
    const float* ad3 = (const float*)d_in[12];
    const float* b3  = (const float*)d_in[13];
    const float* lw  = (const float*)d_in[14];
    const float* lb  = (const float*)d_in[15];
    float* out = (float*)d_out;

    int B = in_sizes[1] / (32 * 15);
    int R = in_sizes[0] / (B * 32);
    int G = B * R;

    prep_kernel<<<177, 128>>>(W1, W2, W3, as3, ad3);
    gat_fused_kernel<<<G, THREADS>>>(xs, pe, as1, ad1, b1,
                                     as2, ad2, b2,
                                     b3, lw, lb, out, R);
}

// round 11
// speedup vs baseline: 2.2466x; 1.2919x over previous
#include <cuda_runtime.h>

// GAT over 16384 independent 32-node cliques, fully fused: one CTA per graph.
// All matrix products on tensor cores (mma.sync m16n8k8 tf32). Weights are
// pre-shuffled into fragment order (coalesced LDG.128 per B-frag pair) and
// hs is stored pre-rounded to tf32 (no cvt on the hot loads).

#define NCOL 32
#define HEADS 4
#define FH 128
#define FHP 132         // hs row stride: 4*row+col bank pattern for frag loads
#define F3 24
#define XINP 20
#define ASTR 36         // alpha row stride
#define THREADS 128
#define NEG_SLOPE 0.2f

typedef unsigned long long u64;

__device__ float W1p_g[16 * FH];    // fragment-ordered tf32 weights
__device__ float W2p_g[FH * FH];
__device__ float W3f_g[4 * 8 * 128];
__device__ float as3p_g[32];
__device__ float ad3p_g[32];

__device__ __forceinline__ float lrelu(float x) { return x > 0.f ? x : NEG_SLOPE * x; }

__device__ __forceinline__ u64 pack2(float a, float b) {
    u64 r; asm("mov.b64 %0,{%1,%2};" : "=l"(r) : "f"(a), "f"(b)); return r;
}
__device__ __forceinline__ float2 unpack2(u64 v) {
    float2 r; asm("mov.b64 {%0,%1},%2;" : "=f"(r.x), "=f"(r.y) : "l"(v)); return r;
}
__device__ __forceinline__ void fma2(u64 &d, u64 a, u64 b) {
    asm("fma.rn.f32x2 %0,%1,%2,%0;" : "+l"(d) : "l"(a), "l"(b));
}
__device__ __forceinline__ void add2(u64 &d, u64 a) {
    asm("add.rn.f32x2 %0,%0,%1;" : "+l"(d) : "l"(a));
}
__device__ __forceinline__ u64 shfl_xor_u64(u64 v, int m) {
    unsigned lo, hi;
    asm("mov.b64 {%0,%1},%2;" : "=r"(lo), "=r"(hi) : "l"(v));
    lo = __shfl_xor_sync(0xffffffffu, lo, m);
    hi = __shfl_xor_sync(0xffffffffu, hi, m);
    u64 r; asm("mov.b64 %0,{%1,%2};" : "=l"(r) : "r"(lo), "r"(hi));
    return r;
}
__device__ __forceinline__ unsigned cvt_tf32(float x) {
    unsigned r; asm("cvt.rna.tf32.f32 %0, %1;" : "=r"(r) : "f"(x)); return r;
}
__device__ __forceinline__ float tf32f(float x) { return __uint_as_float(cvt_tf32(x)); }

__device__ __forceinline__ void mma_t(float c[4], const unsigned a[4], const unsigned b[2]) {
    asm("mma.sync.aligned.m16n8k8.row.col.f32.tf32.tf32.f32 "
        "{%0,%1,%2,%3}, {%4,%5,%6,%7}, {%8,%9}, {%0,%1,%2,%3};"
        : "+f"(c[0]), "+f"(c[1]), "+f"(c[2]), "+f"(c[3])
        : "r"(a[0]), "r"(a[1]), "r"(a[2]), "r"(a[3]), "r"(b[0]), "r"(b[1]));
}

// Fragment-order the weights: per (warp,nt) unit, lane (qr,qc) gets
// [bf0(kt),bf1(kt),bf0(kt+1),bf1(kt+1)] contiguously (one LDG.128).
__global__ void prep_kernel(const float* __restrict__ W1, const float* __restrict__ W2,
                            const float* __restrict__ W3, const float* __restrict__ as3,
                            const float* __restrict__ ad3) {
    int idx = blockIdx.x * blockDim.x + threadIdx.x;
    if (idx < 2048) {                                   // W1p: unit=w*4+nt (16), 1 f4/lane
        int i = idx;
        int j = i & 3, lane = (i >> 2) & 31, unit = i >> 7;
        int qr = lane >> 2, qc = lane & 3;
        int w = unit >> 2, nt = unit & 3;
        int kt = j >> 1, sel = j & 1;
        int row = 8 * kt + qc + 4 * sel;
        int col = 32 * w + 8 * nt + qr;
        W1p_g[i] = tf32f(W1[row * FH + col]);
    } else if (idx < 18432) {                           // W2p: unit (16) x m (8)
        int i = idx - 2048;
        int j = i & 3, lane = (i >> 2) & 31, m = (i >> 7) & 7, unit = i >> 10;
        int qr = lane >> 2, qc = lane & 3;
        int w = unit >> 2, nt = unit & 3;
        int kt = 2 * m + (j >> 1), sel = j & 1;
        int row = 8 * kt + qc + 4 * sel;
        int col = 32 * w + 8 * nt + qr;
        W2p_g[i] = tf32f(W2[row * FH + col]);
    } else if (idx < 22528) {                           // W3f: w (4) x m (8)
        int i = idx - 18432;
        int j = i & 3, lane = (i >> 2) & 31, m = (i >> 7) & 7, w = i >> 10;
        int qr = lane >> 2, qc = lane & 3;
        int kt = 2 * m + (j >> 1), sel = j & 1;
        int row = 8 * kt + qc + 4 * sel;
        W3f_g[i] = (qr < 6) ? tf32f(W3[row * F3 + w * 6 + qr]) : 0.f;
    } else if (idx < 22560) {
        int i = idx - 22528, h = i >> 3, d = i & 7;
        as3p_g[i] = (d < 6) ? as3[h * 6 + d] : 0.f;
    } else if (idx < 22592) {
        int i = idx - 22560, h = i >> 3, d = i & 7;
        ad3p_g[i] = (d < 6) ? ad3[h * 6 + d] : 0.f;
    }
}

__device__ __forceinline__ void softmax_to_alpha(
    const float* __restrict__ s_src_blk, float sdst,
    float (*__restrict__ alpha)[ASTR], int lane)
{
    float e[NCOL];
    float m = -1e30f;
#pragma unroll
    for (int q = 0; q < 8; q++) {
        float4 sv = *(const float4*)&s_src_blk[4 * q];
        e[4*q+0] = lrelu(sdst + sv.x);
        e[4*q+1] = lrelu(sdst + sv.y);
        e[4*q+2] = lrelu(sdst + sv.z);
        e[4*q+3] = lrelu(sdst + sv.w);
    }
#pragma unroll
    for (int j = 0; j < NCOL; j++) m = fmaxf(m, e[j]);
    float sum = 0.f;
#pragma unroll
    for (int j = 0; j < NCOL; j++) {
        e[j] = __expf(e[j] - m);
        sum += e[j];
    }
    const float rinv = 1.f / sum;
#pragma unroll
    for (int q = 0; q < 8; q++) {
        float4 v;
        v.x = tf32f(e[4*q+0] * rinv);
        v.y = tf32f(e[4*q+1] * rinv);
        v.z = tf32f(e[4*q+2] * rinv);
        v.w = tf32f(e[4*q+3] * rinv);
        *(float4*)&alpha[lane][4 * q] = v;
    }
}

// attention for D=32 head: scores + softmax + MMA aggregation, in-place on hs.
__device__ __forceinline__ void attn32(
    float (*__restrict__ hs)[FHP],
    float (*__restrict__ alpha)[ASTR],
    const float* __restrict__ a_src, const float* __restrict__ a_dst,
    const float* __restrict__ bias,
    float* __restrict__ s_src, float* __restrict__ s_dst,
    int w, int lane, int qr, int qc)
{
    const int c0 = 32 * w;
    __syncwarp();

    // phase 1: fp32 scores for node n = lane (hs pre-rounded tf32)
    {
        const ulonglong2* hp = (const ulonglong2*)&hs[lane][c0];
        const ulonglong2* ap = (const ulonglong2*)(a_src + c0);
        const ulonglong2* dp = (const ulonglong2*)(a_dst + c0);
        u64 ss2 = 0, sd2 = 0;
#pragma unroll
        for (int q = 0; q < 8; q++) {
            ulonglong2 hq = hp[q];
            ulonglong2 aq = ap[q];
            ulonglong2 dq = dp[q];
            fma2(ss2, hq.x, aq.x); fma2(ss2, hq.y, aq.y);
            fma2(sd2, hq.x, dq.x); fma2(sd2, hq.y, dq.y);
        }
        float2 s2 = unpack2(ss2);
        float2 d2 = unpack2(sd2);
        s_src[w * NCOL + lane] = s2.x + s2.y;
        s_dst[w * NCOL + lane] = d2.x + d2.y;
    }
    __syncwarp();

    softmax_to_alpha(&s_src[w * NCOL], s_dst[w * NCOL + lane], alpha, lane);
    __syncwarp();

    // phase 3: MMA out(32x32) = alpha @ h_head (all operands already tf32 bits)
    float C[2][4][4];
#pragma unroll
    for (int mb = 0; mb < 2; mb++)
#pragma unroll
        for (int nt = 0; nt < 4; nt++)
#pragma unroll
            for (int i = 0; i < 4; i++) C[mb][nt][i] = 0.f;

#pragma unroll
    for (int kt = 0; kt < 4; kt++) {
        const int k0 = 8 * kt;
        unsigned a[2][4];
#pragma unroll
        for (int mb = 0; mb < 2; mb++) {
            const int r0 = 16 * mb + qr;
            a[mb][0] = __float_as_uint(alpha[r0][k0 + qc]);
            a[mb][1] = __float_as_uint(alpha[r0 + 8][k0 + qc]);
            a[mb][2] = __float_as_uint(alpha[r0][k0 + qc + 4]);
            a[mb][3] = __float_as_uint(alpha[r0 + 8][k0 + qc + 4]);
        }
#pragma unroll
        for (int nt = 0; nt < 4; nt++) {
            unsigned bf[2];
            bf[0] = __float_as_uint(hs[k0 + qc][c0 + 8 * nt + qr]);
            bf[1] = __float_as_uint(hs[k0 + qc + 4][c0 + 8 * nt + qr]);
#pragma unroll
            for (int mb = 0; mb < 2; mb++) mma_t(C[mb][nt], a[mb], bf);
        }
    }
    // epilogue: + bias, round to tf32, in-place store
#pragma unroll
    for (int nt = 0; nt < 4; nt++) {
        const int c = c0 + 8 * nt + 2 * qc;
        float b0 = bias[c], b1 = bias[c + 1];
#pragma unroll
        for (int mb = 0; mb < 2; mb++) {
            *(float2*)&hs[16 * mb + qr][c] =
                make_float2(tf32f(C[mb][nt][0] + b0), tf32f(C[mb][nt][1] + b1));
            *(float2*)&hs[16 * mb + qr + 8][c] =
                make_float2(tf32f(C[mb][nt][2] + b0), tf32f(C[mb][nt][3] + b1));
        }
    }
}

__global__ void __launch_bounds__(THREADS, 6) gat_fused_kernel(
    const float* __restrict__ xs,
    const float* __restrict__ pe,
    const float* __restrict__ as1, const float* __restrict__ ad1,
    const float* __restrict__ b1,
    const float* __restrict__ as2, const float* __restrict__ ad2,
    const float* __restrict__ b2,
    const float* __restrict__ b3,
    const float* __restrict__ lw,
    const float* __restrict__ lb,
    float* __restrict__ out,
    int R)
{
    __shared__ float hs[NCOL][FHP];
    __shared__ float alphas[HEADS][NCOL][ASTR];
    __shared__ float s_src[HEADS * NCOL];
    __shared__ float s_dst[HEADS * NCOL];
    __shared__ float cs[F3];

    float (*xin)[XINP] = (float(*)[XINP]) & alphas[0][0][0];

    const int g = blockIdx.x;
    const int b = g / R;
    const int r = g - b * R;
    const int t = threadIdx.x;
    const int lane = t & 31;
    const int w = t >> 5;
    const int qr = lane >> 2;
    const int qc = lane & 3;

    // ---- build input features (pre-rounded tf32) ----
    for (int idx = t; idx < NCOL * 16; idx += THREADS) {
        int n = idx >> 4, f = idx & 15;
        float v;
        if (f == 0) v = xs[(size_t)(b * R + r) * NCOL + n];
        else        v = pe[(b * NCOL + n) * 15 + (f - 1)];
        xin[n][f] = tf32f(v);
    }
    __syncthreads();

    // ---- layer 1 GEMM (tensor): warp w -> out cols 32w..32w+31 ----
    {
        float C[2][4][4];
#pragma unroll
        for (int mb = 0; mb < 2; mb++)
#pragma unroll
            for (int nt = 0; nt < 4; nt++)
#pragma unroll
                for (int i = 0; i < 4; i++) C[mb][nt][i] = 0.f;

        unsigned a[2][2][4];
#pragma unroll
        for (int kt = 0; kt < 2; kt++) {
            const int k0 = 8 * kt;
#pragma unroll
            for (int mb = 0; mb < 2; mb++) {
                const int r0 = 16 * mb + qr;
                a[kt][mb][0] = __float_as_uint(xin[r0][k0 + qc]);
                a[kt][mb][1] = __float_as_uint(xin[r0 + 8][k0 + qc]);
                a[kt][mb][2] = __float_as_uint(xin[r0][k0 + qc + 4]);
                a[kt][mb][3] = __float_as_uint(xin[r0 + 8][k0 + qc + 4]);
            }
        }
        const float4* W1p4 = (const float4*)W1p_g;
#pragma unroll
        for (int nt = 0; nt < 4; nt++) {
            float4 wv = W1p4[(w * 4 + nt) * 32 + lane];   // coalesced 512B
            unsigned bf0[2] = { __float_as_uint(wv.x), __float_as_uint(wv.y) };
            unsigned bf1[2] = { __float_as_uint(wv.z), __float_as_uint(wv.w) };
#pragma unroll
            for (int mb = 0; mb < 2; mb++) {
                mma_t(C[mb][nt], a[0][mb], bf0);
                mma_t(C[mb][nt], a[1][mb], bf1);
            }
        }
#pragma unroll
        for (int mb = 0; mb < 2; mb++)
#pragma unroll
            for (int nt = 0; nt < 4; nt++) {
                const int c = 32 * w + nt * 8 + 2 * qc;
                *(float2*)&hs[16 * mb + qr][c] =
                    make_float2(tf32f(C[mb][nt][0]), tf32f(C[mb][nt][1]));
                *(float2*)&hs[16 * mb + qr + 8][c] =
                    make_float2(tf32f(C[mb][nt][2]), tf32f(C[mb][nt][3]));
            }
    }
    __syncthreads();   // xin reads done -> alphas writable; hs visible

    attn32(hs, alphas[w], as1, ad1, b1, s_src, s_dst, w, lane, qr, qc);
    __syncthreads();

    // ---- layer 2 GEMM (tensor): warp w -> out cols 32w..32w+31 ----
    {
        float C[2][4][4];
#pragma unroll
        for (int mb = 0; mb < 2; mb++)
#pragma unroll
            for (int nt = 0; nt < 4; nt++)
#pragma unroll
                for (int i = 0; i < 4; i++) C[mb][nt][i] = 0.f;

        const float4* W2p4 = (const float4*)W2p_g;
        float4 wv[4];
#pragma unroll 4
        for (int kt = 0; kt < 16; kt++) {
            const int k0 = 8 * kt;
            unsigned a[2][4];
#pragma unroll
            for (int mb = 0; mb < 2; mb++) {
                const int r0 = 16 * mb + qr;
                a[mb][0] = __float_as_uint(hs[r0][k0 + qc]);
                a[mb][1] = __float_as_uint(hs[r0 + 8][k0 + qc]);
                a[mb][2] = __float_as_uint(hs[r0][k0 + qc + 4]);
                a[mb][3] = __float_as_uint(hs[r0 + 8][k0 + qc + 4]);
            }
            if ((kt & 1) == 0) {
                const int m = kt >> 1;
#pragma unroll
                for (int nt = 0; nt < 4; nt++)
                    wv[nt] = W2p4[((w * 4 + nt) * 8 + m) * 32 + lane];   // coalesced
            }
#pragma unroll
            for (int nt = 0; nt < 4; nt++) {
                unsigned bf[2];
                if ((kt & 1) == 0) { bf[0] = __float_as_uint(wv[nt].x); bf[1] = __float_as_uint(wv[nt].y); }
                else               { bf[0] = __float_as_uint(wv[nt].z); bf[1] = __float_as_uint(wv[nt].w); }
#pragma unroll
                for (int mb = 0; mb < 2; mb++) mma_t(C[mb][nt], a[mb], bf);
            }
        }
        __syncthreads();   // all warps done reading hs before overwrite
#pragma unroll
        for (int mb = 0; mb < 2; mb++)
#pragma unroll
            for (int nt = 0; nt < 4; nt++) {
                const int c = 32 * w + nt * 8 + 2 * qc;
                *(float2*)&hs[16 * mb + qr][c] =
                    make_float2(tf32f(C[mb][nt][0]), tf32f(C[mb][nt][1]));
                *(float2*)&hs[16 * mb + qr + 8][c] =
                    make_float2(tf32f(C[mb][nt][2]), tf32f(C[mb][nt][3]));
            }
    }
    attn32(hs, alphas[w], as2, ad2, b2, s_src, s_dst, w, lane, qr, qc);
    __syncthreads();

    // ---- layer 3 GEMM (tensor): warp w -> padded cols 8w..8w+7 ----
    {
        float C[2][4];
#pragma unroll
        for (int mb = 0; mb < 2; mb++)
#pragma unroll
            for (int i = 0; i < 4; i++) C[mb][i] = 0.f;

        const float4* W3f4 = (const float4*)W3f_g;
        float4 wv;
#pragma unroll 4
        for (int kt = 0; kt < 16; kt++) {
            const int k0 = 8 * kt;
            unsigned a[2][4];
#pragma unroll
            for (int mb = 0; mb < 2; mb++) {
                const int r0 = 16 * mb + qr;
                a[mb][0] = __float_as_uint(hs[r0][k0 + qc]);
                a[mb][1] = __float_as_uint(hs[r0 + 8][k0 + qc]);
                a[mb][2] = __float_as_uint(hs[r0][k0 + qc + 4]);
                a[mb][3] = __float_as_uint(hs[r0 + 8][k0 + qc + 4]);
            }
            if ((kt & 1) == 0)
                wv = W3f4[(w * 8 + (kt >> 1)) * 32 + lane];   // coalesced
            unsigned bf[2];
            if ((kt & 1) == 0) { bf[0] = __float_as_uint(wv.x); bf[1] = __float_as_uint(wv.y); }
            else               { bf[0] = __float_as_uint(wv.z); bf[1] = __float_as_uint(wv.w); }
#pragma unroll
            for (int mb = 0; mb < 2; mb++) mma_t(C[mb], a[mb], bf);
        }
        __syncthreads();   // all warps done reading hs before writing cols 0..31
#pragma unroll
        for (int mb = 0; mb < 2; mb++) {
            const int c = 8 * w + 2 * qc;
            *(float2*)&hs[16 * mb + qr][c] =
                make_float2(tf32f(C[mb][0]), tf32f(C[mb][1]));
            *(float2*)&hs[16 * mb + qr + 8][c] =
                make_float2(tf32f(C[mb][2]), tf32f(C[mb][3]));
        }
    }
    __syncwarp();

    // ---- layer-3 attention + register tail ----
    {
        const int cp = 8 * w;
        {
            ulonglong2 hq = *(const ulonglong2*)&hs[lane][cp];
            ulonglong2 aq = *(const ulonglong2*)(as3p_g + cp);
            ulonglong2 dq = *(const ulonglong2*)(ad3p_g + cp);
            u64 ss2 = 0, sd2 = 0;
            fma2(ss2, hq.x, aq.x); fma2(ss2, hq.y, aq.y);
            fma2(sd2, hq.x, dq.x); fma2(sd2, hq.y, dq.y);
            float2 s2 = unpack2(ss2);
            float2 d2 = unpack2(sd2);
            s_src[w * NCOL + lane] = s2.x + s2.y;
            s_dst[w * NCOL + lane] = d2.x + d2.y;
        }
        __syncwarp();

        softmax_to_alpha(&s_src[w * NCOL], s_dst[w * NCOL + lane], alphas[w], lane);
        __syncwarp();

        float C[2][4];
#pragma unroll
        for (int mb = 0; mb < 2; mb++)
#pragma unroll
            for (int i = 0; i < 4; i++) C[mb][i] = 0.f;

#pragma unroll
        for (int kt = 0; kt < 4; kt++) {
            const int k0 = 8 * kt;
            unsigned a[2][4];
#pragma unroll
            for (int mb = 0; mb < 2; mb++) {
                const int r0 = 16 * mb + qr;
                a[mb][0] = __float_as_uint(alphas[w][r0][k0 + qc]);
                a[mb][1] = __float_as_uint(alphas[w][r0 + 8][k0 + qc]);
                a[mb][2] = __float_as_uint(alphas[w][r0][k0 + qc + 4]);
                a[mb][3] = __float_as_uint(alphas[w][r0 + 8][k0 + qc + 4]);
            }
            unsigned bf[2];
            bf[0] = __float_as_uint(hs[k0 + qc][cp + qr]);
            bf[1] = __float_as_uint(hs[k0 + qc + 4][cp + qr]);
#pragma unroll
            for (int mb = 0; mb < 2; mb++) mma_t(C[mb], a[mb], bf);
        }

        float se = C[0][0] + C[0][2] + C[1][0] + C[1][2];
        float so = C[0][1] + C[0][3] + C[1][1] + C[1][3];
        u64 p = pack2(se, so);
        add2(p, shfl_xor_u64(p, 4));
        add2(p, shfl_xor_u64(p, 8));
        add2(p, shfl_xor_u64(p, 16));
        if (qr == 0 && qc < 3) {
            float2 pv = unpack2(p);
            cs[w * 6 + 2 * qc]     = pv.x * (1.f / 32.f) + b3[w * 6 + 2 * qc];
            cs[w * 6 + 2 * qc + 1] = pv.y * (1.f / 32.f) + b3[w * 6 + 2 * qc + 1];
        }
    }
    __syncthreads();

    // ---- final linear ----
    if (t < 64) {
        float acc = lb[t];
#pragma unroll
        for (int k = 0; k < F3; k++) acc = fmaf(cs[k], lw[k * 64 + t], acc);
        out[(size_t)g * 64 + t] = acc;
    }
}

extern "C" void kernel_launch(void* const* d_in, const int* in_sizes, int n_in,
                              void* d_out, int out_size)
{
    const float* xs  = (const float*)d_in[0];
    const float* pe  = (const float*)d_in[1];
    const float* W1  = (const float*)d_in[2];
    const float* as1 = (const float*)d_in[3];
    const float* ad1 = (const float*)d_in[4];
    const float* b1  = (const float*)d_in[5];
    const float* W2  = (const float*)d_in[6];
    const float* as2 = (const float*)d_in[7];
    const float* ad2 = (const float*)d_in[8];
    const float* b2  = (const float*)d_in[9];
    const float* W3  = (const float*)d_in[10];
    const float* as3 = (const float*)d_in[11];
    const float* ad3 = (const float*)d_in[12];
    const float* b3  = (const float*)d_in[13];
    const float* lw  = (const float*)d_in[14];
    const float* lb  = (const float*)d_in[15];
    float* out = (float*)d_out;

    int B = in_sizes[1] / (32 * 15);
    int R = in_sizes[0] / (B * 32);
    int G = B * R;

    prep_kernel<<<177, 128>>>(W1, W2, W3, as3, ad3);
    gat_fused_kernel<<<G, THREADS>>>(xs, pe, as1, ad1, b1,
                                     as2, ad2, b2,
                                     b3, lw, lb, out, R);
}

// round 12
// speedup vs baseline: 3.7159x; 1.6540x over previous
#include <cuda_runtime.h>
#include <cuda_fp16.h>

// GAT over 16384 independent 32-node cliques, fully fused: one CTA per graph.
// All matrix products on fp16 tensor cores (mma.sync m16n8k16, fp32 accum).
// fp16 carries the same 10-bit mantissa as tf32 but HALF the bytes -> halves
// the L1 wavefront bill. Scores/softmax/bias math stays fp32.

#define NCOL 32
#define HEADS 4
#define FH 128
#define HSTR 136        // hs row stride in halfs (272B; word-stride 68 = 4 mod 32)
#define F3 24
#define XSTR 24         // xin row stride in halfs (word-stride 12: conflict-free)
#define ASTRW 20        // alpha row stride in u32 words (20 mod 32 pattern: conflict-free)
#define THREADS 128
#define NEG_SLOPE 0.2f

typedef unsigned long long u64;

__device__ unsigned W2h_g[8192];   // fragment-ordered fp16x2 weights
__device__ unsigned W1h_g[1024];
__device__ unsigned W3h_g[2048];
__device__ float as3p_g[32];
__device__ float ad3p_g[32];

__device__ __forceinline__ float lrelu(float x) { return x > 0.f ? x : NEG_SLOPE * x; }

__device__ __forceinline__ u64 pack2(float a, float b) {
    u64 r; asm("mov.b64 %0,{%1,%2};" : "=l"(r) : "f"(a), "f"(b)); return r;
}
__device__ __forceinline__ float2 unpack2(u64 v) {
    float2 r; asm("mov.b64 {%0,%1},%2;" : "=f"(r.x), "=f"(r.y) : "l"(v)); return r;
}
__device__ __forceinline__ void add2(u64 &d, u64 a) {
    asm("add.rn.f32x2 %0,%0,%1;" : "+l"(d) : "l"(a));
}
__device__ __forceinline__ u64 shfl_xor_u64(u64 v, int m) {
    unsigned lo, hi;
    asm("mov.b64 {%0,%1},%2;" : "=r"(lo), "=r"(hi) : "l"(v));
    lo = __shfl_xor_sync(0xffffffffu, lo, m);
    hi = __shfl_xor_sync(0xffffffffu, hi, m);
    u64 r; asm("mov.b64 %0,{%1,%2};" : "=l"(r) : "r"(lo), "r"(hi));
    return r;
}
__device__ __forceinline__ unsigned packh2(float lo, float hi) {
    __half2 h = __floats2half2_rn(lo, hi);
    return *(unsigned*)&h;
}
__device__ __forceinline__ float2 h2f2(unsigned v) {
    return __half22float2(*(__half2*)&v);
}
__device__ __forceinline__ void mma_h(float c[4], const unsigned a[4], const unsigned b[2]) {
    asm("mma.sync.aligned.m16n8k16.row.col.f32.f16.f16.f32 "
        "{%0,%1,%2,%3}, {%4,%5,%6,%7}, {%8,%9}, {%0,%1,%2,%3};"
        : "+f"(c[0]), "+f"(c[1]), "+f"(c[2]), "+f"(c[3])
        : "r"(a[0]), "r"(a[1]), "r"(a[2]), "r"(a[3]), "r"(b[0]), "r"(b[1]));
}

__global__ void prep_kernel(const float* __restrict__ W1, const float* __restrict__ W2,
                            const float* __restrict__ W3, const float* __restrict__ as3,
                            const float* __restrict__ ad3) {
    int idx = blockIdx.x * blockDim.x + threadIdx.x;
    if (idx < 8192) {            // W2h: (((w*4+nt)*4+m)*32+lane)*4+j
        int j = idx & 3, lane = (idx >> 2) & 31, m = (idx >> 7) & 3, unit = idx >> 9;
        int qr = lane >> 2, qc = lane & 3;
        int w = unit >> 2, nt = unit & 3;
        int kt = 2 * m + (j >> 1);
        int kp = 16 * kt + 2 * qc + ((j & 1) ? 8 : 0);
        int col = 32 * w + 8 * nt + qr;
        W2h_g[idx] = packh2(W2[kp * FH + col], W2[(kp + 1) * FH + col]);
    } else if (idx < 9216) {     // W1h: ((w*4+nt)*32+lane)*2+j
        int i = idx - 8192;
        int j = i & 1, lane = (i >> 1) & 31, unit = i >> 6;
        int qr = lane >> 2, qc = lane & 3;
        int w = unit >> 2, nt = unit & 3;
        int kp = 2 * qc + (j ? 8 : 0);
        int col = 32 * w + 8 * nt + qr;
        W1h_g[i] = packh2(W1[kp * FH + col], W1[(kp + 1) * FH + col]);
    } else if (idx < 11264) {    // W3h: ((w*4+m)*32+lane)*4+j  (padded n=qr, zero qr>=6)
        int i = idx - 9216;
        int j = i & 3, lane = (i >> 2) & 31, m = (i >> 7) & 3, w = i >> 9;
        int qr = lane >> 2, qc = lane & 3;
        int kt = 2 * m + (j >> 1);
        int kp = 16 * kt + 2 * qc + ((j & 1) ? 8 : 0);
        W3h_g[i] = (qr < 6) ? packh2(W3[kp * F3 + w * 6 + qr], W3[(kp + 1) * F3 + w * 6 + qr]) : 0u;
    } else if (idx < 11296) {
        int i = idx - 11264, h = i >> 3, d = i & 7;
        as3p_g[i] = (d < 6) ? as3[h * 6 + d] : 0.f;
    } else if (idx < 11328) {
        int i = idx - 11296, h = i >> 3, d = i & 7;
        ad3p_g[i] = (d < 6) ? ad3[h * 6 + d] : 0.f;
    }
}

__global__ void __launch_bounds__(THREADS, 6) gat_fused_kernel(
    const float* __restrict__ xs,
    const float* __restrict__ pe,
    const float* __restrict__ as1, const float* __restrict__ ad1,
    const float* __restrict__ b1,
    const float* __restrict__ as2, const float* __restrict__ ad2,
    const float* __restrict__ b2,
    const float* __restrict__ b3,
    const float* __restrict__ lw,
    const float* __restrict__ lb,
    float* __restrict__ out,
    int R)
{
    __shared__ __half hs[NCOL][HSTR];                 // 8.5 KB
    __shared__ unsigned alphas[HEADS][NCOL][ASTRW];   // 10 KB (fp16x2 alpha words)
    __shared__ float s_src[HEADS * NCOL];
    __shared__ float s_dst[HEADS * NCOL];
    __shared__ float cs[F3];

    __half (*xin)[XSTR] = (__half(*)[XSTR]) & alphas[0][0][0];  // overlay

    const int g = blockIdx.x;
    const int b = g / R;
    const int r = g - b * R;
    const int t = threadIdx.x;
    const int lane = t & 31;
    const int w = t >> 5;
    const int qr = lane >> 2;
    const int qc = lane & 3;

    // ---- build input features (fp16) ----
    for (int idx = t; idx < NCOL * 16; idx += THREADS) {
        int n = idx >> 4, f = idx & 15;
        float v;
        if (f == 0) v = xs[(size_t)(b * R + r) * NCOL + n];
        else        v = pe[(b * NCOL + n) * 15 + (f - 1)];
        xin[n][f] = __float2half_rn(v);
    }
    __syncthreads();

    // ================= layer 1 GEMM: warp w -> out cols 32w..32w+31 =================
    {
        float C[2][4][4];
#pragma unroll
        for (int mb = 0; mb < 2; mb++)
#pragma unroll
            for (int nt = 0; nt < 4; nt++)
#pragma unroll
                for (int i = 0; i < 4; i++) C[mb][nt][i] = 0.f;

        unsigned a[2][4];
#pragma unroll
        for (int mb = 0; mb < 2; mb++) {
            const int r0 = 16 * mb + qr;
            a[mb][0] = *(const unsigned*)&xin[r0][2 * qc];
            a[mb][1] = *(const unsigned*)&xin[r0 + 8][2 * qc];
            a[mb][2] = *(const unsigned*)&xin[r0][2 * qc + 8];
            a[mb][3] = *(const unsigned*)&xin[r0 + 8][2 * qc + 8];
        }
        const uint2* W1h2 = (const uint2*)W1h_g;
#pragma unroll
        for (int nt = 0; nt < 4; nt++) {
            uint2 bw = W1h2[(w * 4 + nt) * 32 + lane];   // coalesced
            unsigned bf[2] = { bw.x, bw.y };
#pragma unroll
            for (int mb = 0; mb < 2; mb++) mma_h(C[mb][nt], a[mb], bf);
        }
#pragma unroll
        for (int mb = 0; mb < 2; mb++)
#pragma unroll
            for (int nt = 0; nt < 4; nt++) {
                const int c = 32 * w + 8 * nt + 2 * qc;
                *(unsigned*)&hs[16 * mb + qr][c]     = packh2(C[mb][nt][0], C[mb][nt][1]);
                *(unsigned*)&hs[16 * mb + qr + 8][c] = packh2(C[mb][nt][2], C[mb][nt][3]);
            }
    }
    __syncthreads();   // xin reads done -> alphas writable; hs cross-warp not needed yet

    // ================= attention layers 1 & 2 (macro-free, inline twice) ============
#pragma unroll
    for (int layer = 0; layer < 2; layer++) {
        const float* a_src = layer ? as2 : as1;
        const float* a_dst = layer ? ad2 : ad1;
        const float* bias  = layer ? b2  : b1;
        const int c0 = 32 * w;
        __syncwarp();

        // phase 1: fp32 scores for node n = lane
        {
            const uint4* hp = (const uint4*)&hs[lane][c0];
            const float4* ap = (const float4*)(a_src + c0);
            const float4* dp = (const float4*)(a_dst + c0);
            float ss = 0.f, sd = 0.f;
#pragma unroll
            for (int q = 0; q < 4; q++) {
                uint4 u = hp[q];
                float2 f0 = h2f2(u.x), f1 = h2f2(u.y), f2 = h2f2(u.z), f3 = h2f2(u.w);
                float4 a0 = ap[2 * q], a1 = ap[2 * q + 1];
                float4 d0 = dp[2 * q], d1 = dp[2 * q + 1];
                ss = fmaf(f0.x, a0.x, fmaf(f0.y, a0.y, fmaf(f1.x, a0.z, fmaf(f1.y, a0.w, ss))));
                ss = fmaf(f2.x, a1.x, fmaf(f2.y, a1.y, fmaf(f3.x, a1.z, fmaf(f3.y, a1.w, ss))));
                sd = fmaf(f0.x, d0.x, fmaf(f0.y, d0.y, fmaf(f1.x, d0.z, fmaf(f1.y, d0.w, sd))));
                sd = fmaf(f2.x, d1.x, fmaf(f2.y, d1.y, fmaf(f3.x, d1.z, fmaf(f3.y, d1.w, sd))));
            }
            s_src[w * NCOL + lane] = ss;
            s_dst[w * NCOL + lane] = sd;
        }
        __syncwarp();

        // phase 2: softmax; store alpha as fp16x2 words
        {
            const float sdst = s_dst[w * NCOL + lane];
            float e[NCOL];
            float m = -1e30f;
#pragma unroll
            for (int q = 0; q < 8; q++) {
                float4 sv = *(const float4*)&s_src[w * NCOL + 4 * q];
                e[4*q+0] = lrelu(sdst + sv.x);
                e[4*q+1] = lrelu(sdst + sv.y);
                e[4*q+2] = lrelu(sdst + sv.z);
                e[4*q+3] = lrelu(sdst + sv.w);
            }
#pragma unroll
            for (int j = 0; j < NCOL; j++) m = fmaxf(m, e[j]);
            float sum = 0.f;
#pragma unroll
            for (int j = 0; j < NCOL; j++) {
                e[j] = __expf(e[j] - m);
                sum += e[j];
            }
            const float rinv = 1.f / sum;
#pragma unroll
            for (int q = 0; q < 4; q++) {
                uint4 v;
                v.x = packh2(e[8*q+0] * rinv, e[8*q+1] * rinv);
                v.y = packh2(e[8*q+2] * rinv, e[8*q+3] * rinv);
                v.z = packh2(e[8*q+4] * rinv, e[8*q+5] * rinv);
                v.w = packh2(e[8*q+6] * rinv, e[8*q+7] * rinv);
                *(uint4*)&alphas[w][lane][4 * q] = v;
            }
        }
        __syncwarp();

        // phase 3: MMA out(32x32) = alpha @ h_head, in-place (warp-local columns)
        {
            float C[2][4][4];
#pragma unroll
            for (int mb = 0; mb < 2; mb++)
#pragma unroll
                for (int nt = 0; nt < 4; nt++)
#pragma unroll
                    for (int i = 0; i < 4; i++) C[mb][nt][i] = 0.f;

#pragma unroll
            for (int kt = 0; kt < 2; kt++) {
                unsigned a[2][4];
#pragma unroll
                for (int mb = 0; mb < 2; mb++) {
                    const int r0 = 16 * mb + qr;
                    a[mb][0] = alphas[w][r0][8 * kt + qc];
                    a[mb][1] = alphas[w][r0 + 8][8 * kt + qc];
                    a[mb][2] = alphas[w][r0][8 * kt + qc + 4];
                    a[mb][3] = alphas[w][r0 + 8][8 * kt + qc + 4];
                }
#pragma unroll
                for (int nt = 0; nt < 4; nt++) {
                    const int col = c0 + 8 * nt + qr;
                    unsigned x0 = *(const unsigned short*)&hs[16 * kt + 2 * qc][col];
                    unsigned x1 = *(const unsigned short*)&hs[16 * kt + 2 * qc + 1][col];
                    unsigned x2 = *(const unsigned short*)&hs[16 * kt + 2 * qc + 8][col];
                    unsigned x3 = *(const unsigned short*)&hs[16 * kt + 2 * qc + 9][col];
                    unsigned bf[2] = { x0 | (x1 << 16), x2 | (x3 << 16) };
#pragma unroll
                    for (int mb = 0; mb < 2; mb++) mma_h(C[mb][nt], a[mb], bf);
                }
            }
            // epilogue: + bias, pack fp16, in-place store (loads precede stores)
#pragma unroll
            for (int nt = 0; nt < 4; nt++) {
                const int c = c0 + 8 * nt + 2 * qc;
                float bb0 = bias[c], bb1 = bias[c + 1];
#pragma unroll
                for (int mb = 0; mb < 2; mb++) {
                    *(unsigned*)&hs[16 * mb + qr][c] =
                        packh2(C[mb][nt][0] + bb0, C[mb][nt][1] + bb1);
                    *(unsigned*)&hs[16 * mb + qr + 8][c] =
                        packh2(C[mb][nt][2] + bb0, C[mb][nt][3] + bb1);
                }
            }
        }
        __syncthreads();   // next GEMM reads all columns

        // ---- GEMM after attention (layer==0 -> GEMM2; layer==1 -> GEMM3) ----
        if (layer == 0) {
            float C[2][4][4];
#pragma unroll
            for (int mb = 0; mb < 2; mb++)
#pragma unroll
                for (int nt = 0; nt < 4; nt++)
#pragma unroll
                    for (int i = 0; i < 4; i++) C[mb][nt][i] = 0.f;

            const uint4* W2h4 = (const uint4*)W2h_g;
#pragma unroll
            for (int m = 0; m < 4; m++) {
                uint4 wv[4];
#pragma unroll
                for (int nt = 0; nt < 4; nt++)
                    wv[nt] = W2h4[((w * 4 + nt) * 4 + m) * 32 + lane];   // coalesced
#pragma unroll
                for (int hh = 0; hh < 2; hh++) {
                    const int kt = 2 * m + hh;
                    unsigned a[2][4];
#pragma unroll
                    for (int mb = 0; mb < 2; mb++) {
                        const int r0 = 16 * mb + qr;
                        a[mb][0] = *(const unsigned*)&hs[r0][16 * kt + 2 * qc];
                        a[mb][1] = *(const unsigned*)&hs[r0 + 8][16 * kt + 2 * qc];
                        a[mb][2] = *(const unsigned*)&hs[r0][16 * kt + 2 * qc + 8];
                        a[mb][3] = *(const unsigned*)&hs[r0 + 8][16 * kt + 2 * qc + 8];
                    }
#pragma unroll
                    for (int nt = 0; nt < 4; nt++) {
                        unsigned bf[2];
                        if (hh == 0) { bf[0] = wv[nt].x; bf[1] = wv[nt].y; }
                        else         { bf[0] = wv[nt].z; bf[1] = wv[nt].w; }
#pragma unroll
                        for (int mb = 0; mb < 2; mb++) mma_h(C[mb][nt], a[mb], bf);
                    }
                }
            }
            __syncthreads();   // all warps done reading hs before overwrite
#pragma unroll
            for (int mb = 0; mb < 2; mb++)
#pragma unroll
                for (int nt = 0; nt < 4; nt++) {
                    const int c = 32 * w + 8 * nt + 2 * qc;
                    *(unsigned*)&hs[16 * mb + qr][c]     = packh2(C[mb][nt][0], C[mb][nt][1]);
                    *(unsigned*)&hs[16 * mb + qr + 8][c] = packh2(C[mb][nt][2], C[mb][nt][3]);
                }
        } else {
            // GEMM3: warp w -> padded cols 8w..8w+7
            float C[2][4];
#pragma unroll
            for (int mb = 0; mb < 2; mb++)
#pragma unroll
                for (int i = 0; i < 4; i++) C[mb][i] = 0.f;

            const uint4* W3h4 = (const uint4*)W3h_g;
#pragma unroll
            for (int m = 0; m < 4; m++) {
                uint4 wv = W3h4[(w * 4 + m) * 32 + lane];   // coalesced
#pragma unroll
                for (int hh = 0; hh < 2; hh++) {
                    const int kt = 2 * m + hh;
                    unsigned a[2][4];
#pragma unroll
                    for (int mb = 0; mb < 2; mb++) {
                        const int r0 = 16 * mb + qr;
                        a[mb][0] = *(const unsigned*)&hs[r0][16 * kt + 2 * qc];
                        a[mb][1] = *(const unsigned*)&hs[r0 + 8][16 * kt + 2 * qc];
                        a[mb][2] = *(const unsigned*)&hs[r0][16 * kt + 2 * qc + 8];
                        a[mb][3] = *(const unsigned*)&hs[r0 + 8][16 * kt + 2 * qc + 8];
                    }
                    unsigned bf[2];
                    if (hh == 0) { bf[0] = wv.x; bf[1] = wv.y; }
                    else         { bf[0] = wv.z; bf[1] = wv.w; }
#pragma unroll
                    for (int mb = 0; mb < 2; mb++) mma_h(C[mb], a[mb], bf);
                }
            }
            __syncthreads();   // all warps done reading hs before writing cols 0..31
#pragma unroll
            for (int mb = 0; mb < 2; mb++) {
                const int c = 8 * w + 2 * qc;
                *(unsigned*)&hs[16 * mb + qr][c]     = packh2(C[mb][0], C[mb][1]);
                *(unsigned*)&hs[16 * mb + qr + 8][c] = packh2(C[mb][2], C[mb][3]);
            }
        }
    }
    __syncwarp();

    // ================= layer-3 attention + register tail ============================
    {
        const int cp = 8 * w;

        // phase 1: scores from padded 8 cols (d=6,7 are exact zeros)
        {
            uint4 u = *(const uint4*)&hs[lane][cp];
            float2 f0 = h2f2(u.x), f1 = h2f2(u.y), f2 = h2f2(u.z), f3 = h2f2(u.w);
            const float4* ap = (const float4*)(as3p_g + cp);
            const float4* dp = (const float4*)(ad3p_g + cp);
            float4 a0 = ap[0], a1 = ap[1];
            float4 d0 = dp[0], d1 = dp[1];
            float ss, sd;
            ss = fmaf(f0.x, a0.x, fmaf(f0.y, a0.y, fmaf(f1.x, a0.z, f1.y * a0.w)));
            ss = fmaf(f2.x, a1.x, fmaf(f2.y, a1.y, fmaf(f3.x, a1.z, fmaf(f3.y, a1.w, ss))));
            sd = fmaf(f0.x, d0.x, fmaf(f0.y, d0.y, fmaf(f1.x, d0.z, f1.y * d0.w)));
            sd = fmaf(f2.x, d1.x, fmaf(f2.y, d1.y, fmaf(f3.x, d1.z, fmaf(f3.y, d1.w, sd))));
            s_src[w * NCOL + lane] = ss;
            s_dst[w * NCOL + lane] = sd;
        }
        __syncwarp();

        // phase 2: softmax -> alpha fp16x2
        {
            const float sdst = s_dst[w * NCOL + lane];
            float e[NCOL];
            float m = -1e30f;
#pragma unroll
            for (int q = 0; q < 8; q++) {
                float4 sv = *(const float4*)&s_src[w * NCOL + 4 * q];
                e[4*q+0] = lrelu(sdst + sv.x);
                e[4*q+1] = lrelu(sdst + sv.y);
                e[4*q+2] = lrelu(sdst + sv.z);
                e[4*q+3] = lrelu(sdst + sv.w);
            }
#pragma unroll
            for (int j = 0; j < NCOL; j++) m = fmaxf(m, e[j]);
            float sum = 0.f;
#pragma unroll
            for (int j = 0; j < NCOL; j++) {
                e[j] = __expf(e[j] - m);
                sum += e[j];
            }
            const float rinv = 1.f / sum;
#pragma unroll
            for (int q = 0; q < 4; q++) {
                uint4 v;
                v.x = packh2(e[8*q+0] * rinv, e[8*q+1] * rinv);
                v.y = packh2(e[8*q+2] * rinv, e[8*q+3] * rinv);
                v.z = packh2(e[8*q+4] * rinv, e[8*q+5] * rinv);
                v.w = packh2(e[8*q+6] * rinv, e[8*q+7] * rinv);
                *(uint4*)&alphas[w][lane][4 * q] = v;
            }
        }
        __syncwarp();

        // MMA: h3post = alpha @ h3 (N=8 padded), C stays in registers
        float C[2][4];
#pragma unroll
        for (int mb = 0; mb < 2; mb++)
#pragma unroll
            for (int i = 0; i < 4; i++) C[mb][i] = 0.f;

#pragma unroll
        for (int kt = 0; kt < 2; kt++) {
            unsigned a[2][4];
#pragma unroll
            for (int mb = 0; mb < 2; mb++) {
                const int r0 = 16 * mb + qr;
                a[mb][0] = alphas[w][r0][8 * kt + qc];
                a[mb][1] = alphas[w][r0 + 8][8 * kt + qc];
                a[mb][2] = alphas[w][r0][8 * kt + qc + 4];
                a[mb][3] = alphas[w][r0 + 8][8 * kt + qc + 4];
            }
            const int col = cp + qr;
            unsigned x0 = *(const unsigned short*)&hs[16 * kt + 2 * qc][col];
            unsigned x1 = *(const unsigned short*)&hs[16 * kt + 2 * qc + 1][col];
            unsigned x2 = *(const unsigned short*)&hs[16 * kt + 2 * qc + 8][col];
            unsigned x3 = *(const unsigned short*)&hs[16 * kt + 2 * qc + 9][col];
            unsigned bf[2] = { x0 | (x1 << 16), x2 | (x3 << 16) };
#pragma unroll
            for (int mb = 0; mb < 2; mb++) mma_h(C[mb], a[mb], bf);
        }

        // tail: node-mean of h3post directly from C fragments
        float se = C[0][0] + C[0][2] + C[1][0] + C[1][2];   // col cp+2qc
        float so = C[0][1] + C[0][3] + C[1][1] + C[1][3];   // col cp+2qc+1
        u64 p = pack2(se, so);
        add2(p, shfl_xor_u64(p, 4));
        add2(p, shfl_xor_u64(p, 8));
        add2(p, shfl_xor_u64(p, 16));
        if (qr == 0 && qc < 3) {
            float2 pv = unpack2(p);
            cs[w * 6 + 2 * qc]     = pv.x * (1.f / 32.f) + b3[w * 6 + 2 * qc];
            cs[w * 6 + 2 * qc + 1] = pv.y * (1.f / 32.f) + b3[w * 6 + 2 * qc + 1];
        }
    }
    __syncthreads();

    // ---- final linear ----
    if (t < 64) {
        float acc = lb[t];
#pragma unroll
        for (int k = 0; k < F3; k++) acc = fmaf(cs[k], lw[k * 64 + t], acc);
        out[(size_t)g * 64 + t] = acc;
    }
}

extern "C" void kernel_launch(void* const* d_in, const int* in_sizes, int n_in,
                              void* d_out, int out_size)
{
    const float* xs  = (const float*)d_in[0];
    const float* pe  = (const float*)d_in[1];
    const float* W1  = (const float*)d_in[2];
    const float* as1 = (const float*)d_in[3];
    const float* ad1 = (const float*)d_in[4];
    const float* b1  = (const float*)d_in[5];
    const float* W2  = (const float*)d_in[6];
    const float* as2 = (const float*)d_in[7];
    const float* ad2 = (const float*)d_in[8];
    const float* b2  = (const float*)d_in[9];
    const float* W3  = (const float*)d_in[10];
    const float* as3 = (const float*)d_in[11];
    const float* ad3 = (const float*)d_in[12];
    const float* b3  = (const float*)d_in[13];
    const float* lw  = (const float*)d_in[14];
    const float* lb  = (const float*)d_in[15];
    float* out = (float*)d_out;

    int B = in_sizes[1] / (32 * 15);
    int R = in_sizes[0] / (B * 32);
    int G = B * R;

    prep_kernel<<<89, 128>>>(W1, W2, W3, as3, ad3);
    gat_fused_kernel<<<G, THREADS>>>(xs, pe, as1, ad1, b1,
                                     as2, ad2, b2,
                                     b3, lw, lb, out, R);
}

// round 13
// speedup vs baseline: 3.9277x; 1.0570x over previous
#include <cuda_runtime.h>
#include <cuda_fp16.h>

// GAT over 16384 independent 32-node cliques, fully fused: one CTA per graph.
// fp16 tensor-core everything. Attention scores are folded into the GEMMs as
// an extra 8-column MMA tile (u = W @ a_src/dst precomputed); attention B
// fragments load via ldmatrix.x4.trans. Softmax stays fp32.

#define NCOL 32
#define HEADS 4
#define FH 128
#define HSTR 136        // hs row stride in halfs (272B)
#define F3 24
#define XSTR 24
#define ASTRW 20        // alpha row stride in u32 words
#define THREADS 128
#define NEG_SLOPE 0.2f

typedef unsigned long long u64;

__device__ unsigned W2h_g[8192];   // fragment-ordered fp16x2 weights
__device__ unsigned W1h_g[1024];
__device__ unsigned W3h_g[2048];
__device__ unsigned U1f_g[64];     // fragment-ordered score vectors (W @ a)
__device__ unsigned U2f_g[512];
__device__ unsigned U3f_g[512];

__device__ __forceinline__ float lrelu(float x) { return x > 0.f ? x : NEG_SLOPE * x; }

__device__ __forceinline__ u64 pack2(float a, float b) {
    u64 r; asm("mov.b64 %0,{%1,%2};" : "=l"(r) : "f"(a), "f"(b)); return r;
}
__device__ __forceinline__ float2 unpack2(u64 v) {
    float2 r; asm("mov.b64 {%0,%1},%2;" : "=f"(r.x), "=f"(r.y) : "l"(v)); return r;
}
__device__ __forceinline__ void add2(u64 &d, u64 a) {
    asm("add.rn.f32x2 %0,%0,%1;" : "+l"(d) : "l"(a));
}
__device__ __forceinline__ u64 shfl_xor_u64(u64 v, int m) {
    unsigned lo, hi;
    asm("mov.b64 {%0,%1},%2;" : "=r"(lo), "=r"(hi) : "l"(v));
    lo = __shfl_xor_sync(0xffffffffu, lo, m);
    hi = __shfl_xor_sync(0xffffffffu, hi, m);
    u64 r; asm("mov.b64 %0,{%1,%2};" : "=l"(r) : "r"(lo), "r"(hi));
    return r;
}
__device__ __forceinline__ unsigned packh2(float lo, float hi) {
    __half2 h = __floats2half2_rn(lo, hi);
    return *(unsigned*)&h;
}
__device__ __forceinline__ void mma_h(float c[4], const unsigned a[4], const unsigned b[2]) {
    asm("mma.sync.aligned.m16n8k16.row.col.f32.f16.f16.f32 "
        "{%0,%1,%2,%3}, {%4,%5,%6,%7}, {%8,%9}, {%0,%1,%2,%3};"
        : "+f"(c[0]), "+f"(c[1]), "+f"(c[2]), "+f"(c[3])
        : "r"(a[0]), "r"(a[1]), "r"(a[2]), "r"(a[3]), "r"(b[0]), "r"(b[1]));
}
__device__ __forceinline__ unsigned sptr(const void* p) {
    unsigned a;
    asm("{ .reg .u64 t; cvta.to.shared.u64 t, %1; cvt.u32.u64 %0, t; }" : "=r"(a) : "l"(p));
    return a;
}
__device__ __forceinline__ void ldsm_x4_trans(unsigned &d0, unsigned &d1,
                                              unsigned &d2, unsigned &d3, unsigned addr) {
    asm volatile("ldmatrix.sync.aligned.m8n8.x4.trans.shared.b16 {%0,%1,%2,%3}, [%4];"
                 : "=r"(d0), "=r"(d1), "=r"(d2), "=r"(d3) : "r"(addr));
}

// Scatter the 8-column score tile (C fragments) to s_src/s_dst for head w.
__device__ __forceinline__ void store_scores(const float Cs[2][4],
                                             float* __restrict__ s_src,
                                             float* __restrict__ s_dst,
                                             int w, int qr, int qc)
{
    const int par = w & 1;
    if (qc == (w >> 1)) {
        s_src[32 * w + qr]      = par ? Cs[0][1] : Cs[0][0];
        s_src[32 * w + qr + 8]  = par ? Cs[0][3] : Cs[0][2];
        s_src[32 * w + qr + 16] = par ? Cs[1][1] : Cs[1][0];
        s_src[32 * w + qr + 24] = par ? Cs[1][3] : Cs[1][2];
    }
    if (qc == 2 + (w >> 1)) {
        s_dst[32 * w + qr]      = par ? Cs[0][1] : Cs[0][0];
        s_dst[32 * w + qr + 8]  = par ? Cs[0][3] : Cs[0][2];
        s_dst[32 * w + qr + 16] = par ? Cs[1][1] : Cs[1][0];
        s_dst[32 * w + qr + 24] = par ? Cs[1][3] : Cs[1][2];
    }
}

__global__ void prep_kernel(const float* __restrict__ W1, const float* __restrict__ W2,
                            const float* __restrict__ W3,
                            const float* __restrict__ as1, const float* __restrict__ ad1,
                            const float* __restrict__ as2, const float* __restrict__ ad2,
                            const float* __restrict__ as3, const float* __restrict__ ad3)
{
    int idx = blockIdx.x * blockDim.x + threadIdx.x;
    if (idx < 8192) {            // W2h: (((w*4+nt)*4+m)*32+lane)*4+j
        int j = idx & 3, lane = (idx >> 2) & 31, m = (idx >> 7) & 3, unit = idx >> 9;
        int qr = lane >> 2, qc = lane & 3;
        int w = unit >> 2, nt = unit & 3;
        int kt = 2 * m + (j >> 1);
        int kp = 16 * kt + 2 * qc + ((j & 1) ? 8 : 0);
        int col = 32 * w + 8 * nt + qr;
        W2h_g[idx] = packh2(W2[kp * FH + col], W2[(kp + 1) * FH + col]);
    } else if (idx < 9216) {     // W1h
        int i = idx - 8192;
        int j = i & 1, lane = (i >> 1) & 31, unit = i >> 6;
        int qr = lane >> 2, qc = lane & 3;
        int w = unit >> 2, nt = unit & 3;
        int kp = 2 * qc + (j ? 8 : 0);
        int col = 32 * w + 8 * nt + qr;
        W1h_g[i] = packh2(W1[kp * FH + col], W1[(kp + 1) * FH + col]);
    } else if (idx < 11264) {    // W3h (padded n=qr, zero qr>=6)
        int i = idx - 9216;
        int j = i & 3, lane = (i >> 2) & 31, m = (i >> 7) & 3, w = i >> 9;
        int qr = lane >> 2, qc = lane & 3;
        int kt = 2 * m + (j >> 1);
        int kp = 16 * kt + 2 * qc + ((j & 1) ? 8 : 0);
        W3h_g[i] = (qr < 6) ? packh2(W3[kp * F3 + w * 6 + qr], W3[(kp + 1) * F3 + w * 6 + qr]) : 0u;
    } else if (idx < 11776) {    // U2f: (m*32+lane)*4+j — score cols j=qr (0..3 src, 4..7 dst)
        int i = idx - 11264;
        int jj = i & 3, lane = (i >> 2) & 31, m = i >> 7;
        int qr = lane >> 2, qc = lane & 3;
        int kt = 2 * m + (jj >> 1);
        int kp = 16 * kt + 2 * qc + ((jj & 1) ? 8 : 0);
        const float* av = (qr < 4) ? (as2 + 32 * qr) : (ad2 + 32 * (qr - 4));
        int h = qr & 3;
        float u0 = 0.f, u1 = 0.f;
        for (int d = 0; d < 32; d++) {
            u0 += W2[kp * FH + 32 * h + d] * av[d];
            u1 += W2[(kp + 1) * FH + 32 * h + d] * av[d];
        }
        U2f_g[i] = packh2(u0, u1);
    } else if (idx < 11840) {    // U1f: lane*2+j
        int i = idx - 11776;
        int jj = i & 1, lane = i >> 1;
        int qr = lane >> 2, qc = lane & 3;
        int kp = 2 * qc + (jj ? 8 : 0);
        const float* av = (qr < 4) ? (as1 + 32 * qr) : (ad1 + 32 * (qr - 4));
        int h = qr & 3;
        float u0 = 0.f, u1 = 0.f;
        for (int d = 0; d < 32; d++) {
            u0 += W1[kp * FH + 32 * h + d] * av[d];
            u1 += W1[(kp + 1) * FH + 32 * h + d] * av[d];
        }
        U1f_g[i] = packh2(u0, u1);
    } else if (idx < 12352) {    // U3f: (m*32+lane)*4+j
        int i = idx - 11840;
        int jj = i & 3, lane = (i >> 2) & 31, m = i >> 7;
        int qr = lane >> 2, qc = lane & 3;
        int kt = 2 * m + (jj >> 1);
        int kp = 16 * kt + 2 * qc + ((jj & 1) ? 8 : 0);
        const float* av = (qr < 4) ? (as3 + 6 * qr) : (ad3 + 6 * (qr - 4));
        int h = qr & 3;
        float u0 = 0.f, u1 = 0.f;
        for (int d = 0; d < 6; d++) {
            u0 += W3[kp * F3 + 6 * h + d] * av[d];
            u1 += W3[(kp + 1) * F3 + 6 * h + d] * av[d];
        }
        U3f_g[i] = packh2(u0, u1);
    }
}

__global__ void __launch_bounds__(THREADS, 6) gat_fused_kernel(
    const float* __restrict__ xs,
    const float* __restrict__ pe,
    const float* __restrict__ b1,
    const float* __restrict__ b2,
    const float* __restrict__ b3,
    const float* __restrict__ lw,
    const float* __restrict__ lb,
    float* __restrict__ out,
    int R)
{
    __shared__ __half hs[NCOL][HSTR];
    __shared__ unsigned alphas[HEADS][NCOL][ASTRW];
    __shared__ float s_src[HEADS * NCOL];
    __shared__ float s_dst[HEADS * NCOL];
    __shared__ float cs[F3];

    __half (*xin)[XSTR] = (__half(*)[XSTR]) & alphas[0][0][0];  // overlay

    const int g = blockIdx.x;
    const int b = g / R;
    const int r = g - b * R;
    const int t = threadIdx.x;
    const int lane = t & 31;
    const int w = t >> 5;
    const int qr = lane >> 2;
    const int qc = lane & 3;

    // ---- build input features (fp16) ----
    for (int idx = t; idx < NCOL * 16; idx += THREADS) {
        int n = idx >> 4, f = idx & 15;
        float v;
        if (f == 0) v = xs[(size_t)(b * R + r) * NCOL + n];
        else        v = pe[(b * NCOL + n) * 15 + (f - 1)];
        xin[n][f] = __float2half_rn(v);
    }
    __syncthreads();

    // ================= layer 1 GEMM + scores =================
    {
        float C[2][4][4];
        float Cs[2][4];
#pragma unroll
        for (int mb = 0; mb < 2; mb++) {
#pragma unroll
            for (int nt = 0; nt < 4; nt++)
#pragma unroll
                for (int i = 0; i < 4; i++) C[mb][nt][i] = 0.f;
#pragma unroll
            for (int i = 0; i < 4; i++) Cs[mb][i] = 0.f;
        }

        unsigned a[2][4];
#pragma unroll
        for (int mb = 0; mb < 2; mb++) {
            const int r0 = 16 * mb + qr;
            a[mb][0] = *(const unsigned*)&xin[r0][2 * qc];
            a[mb][1] = *(const unsigned*)&xin[r0 + 8][2 * qc];
            a[mb][2] = *(const unsigned*)&xin[r0][2 * qc + 8];
            a[mb][3] = *(const unsigned*)&xin[r0 + 8][2 * qc + 8];
        }
        const uint2* W1h2 = (const uint2*)W1h_g;
#pragma unroll
        for (int nt = 0; nt < 4; nt++) {
            uint2 bw = W1h2[(w * 4 + nt) * 32 + lane];
            unsigned bf[2] = { bw.x, bw.y };
#pragma unroll
            for (int mb = 0; mb < 2; mb++) mma_h(C[mb][nt], a[mb], bf);
        }
        {
            uint2 uw = ((const uint2*)U1f_g)[lane];
            unsigned bf[2] = { uw.x, uw.y };
#pragma unroll
            for (int mb = 0; mb < 2; mb++) mma_h(Cs[mb], a[mb], bf);
        }
#pragma unroll
        for (int mb = 0; mb < 2; mb++)
#pragma unroll
            for (int nt = 0; nt < 4; nt++) {
                const int c = 32 * w + 8 * nt + 2 * qc;
                *(unsigned*)&hs[16 * mb + qr][c]     = packh2(C[mb][nt][0], C[mb][nt][1]);
                *(unsigned*)&hs[16 * mb + qr + 8][c] = packh2(C[mb][nt][2], C[mb][nt][3]);
            }
        store_scores(Cs, s_src, s_dst, w, qr, qc);
    }
    __syncthreads();   // xin reads done -> alphas writable; hs visible CTA-wide

    // ================= attention layers 1 & 2 + following GEMM =================
#pragma unroll
    for (int layer = 0; layer < 2; layer++) {
        const float* bias = layer ? b2 : b1;
        const int c0 = 32 * w;
        __syncwarp();

        // softmax (scores already in s_src/s_dst from the GEMM epilogue)
        {
            const float sdst = s_dst[w * NCOL + lane];
            float e[NCOL];
            float m = -1e30f;
#pragma unroll
            for (int q = 0; q < 8; q++) {
                float4 sv = *(const float4*)&s_src[w * NCOL + 4 * q];
                e[4*q+0] = lrelu(sdst + sv.x);
                e[4*q+1] = lrelu(sdst + sv.y);
                e[4*q+2] = lrelu(sdst + sv.z);
                e[4*q+3] = lrelu(sdst + sv.w);
            }
#pragma unroll
            for (int j = 0; j < NCOL; j++) m = fmaxf(m, e[j]);
            float sum = 0.f;
#pragma unroll
            for (int j = 0; j < NCOL; j++) {
                e[j] = __expf(e[j] - m);
                sum += e[j];
            }
            const float rinv = 1.f / sum;
#pragma unroll
            for (int q = 0; q < 4; q++) {
                uint4 v;
                v.x = packh2(e[8*q+0] * rinv, e[8*q+1] * rinv);
                v.y = packh2(e[8*q+2] * rinv, e[8*q+3] * rinv);
                v.z = packh2(e[8*q+4] * rinv, e[8*q+5] * rinv);
                v.w = packh2(e[8*q+6] * rinv, e[8*q+7] * rinv);
                *(uint4*)&alphas[w][lane][4 * q] = v;
            }
        }
        __syncwarp();

        // aggregation MMA: out(32x32) = alpha @ h_head, in-place (warp-local cols)
        {
            float C[2][4][4];
#pragma unroll
            for (int mb = 0; mb < 2; mb++)
#pragma unroll
                for (int nt = 0; nt < 4; nt++)
#pragma unroll
                    for (int i = 0; i < 4; i++) C[mb][nt][i] = 0.f;

            unsigned af[2][2][4];
#pragma unroll
            for (int kt = 0; kt < 2; kt++)
#pragma unroll
                for (int mb = 0; mb < 2; mb++) {
                    const int r0 = 16 * mb + qr;
                    af[kt][mb][0] = alphas[w][r0][8 * kt + qc];
                    af[kt][mb][1] = alphas[w][r0 + 8][8 * kt + qc];
                    af[kt][mb][2] = alphas[w][r0][8 * kt + qc + 4];
                    af[kt][mb][3] = alphas[w][r0 + 8][8 * kt + qc + 4];
                }
#pragma unroll
            for (int nt = 0; nt < 4; nt++) {
                unsigned d0, d1, d2, d3;
                ldsm_x4_trans(d0, d1, d2, d3, sptr(&hs[lane][c0 + 8 * nt]));
                unsigned bf0[2] = { d0, d1 };
                unsigned bf1[2] = { d2, d3 };
#pragma unroll
                for (int mb = 0; mb < 2; mb++) {
                    mma_h(C[mb][nt], af[0][mb], bf0);
                    mma_h(C[mb][nt], af[1][mb], bf1);
                }
            }
            // epilogue: + bias, pack fp16, in-place store
#pragma unroll
            for (int nt = 0; nt < 4; nt++) {
                const int c = c0 + 8 * nt + 2 * qc;
                float bb0 = bias[c], bb1 = bias[c + 1];
#pragma unroll
                for (int mb = 0; mb < 2; mb++) {
                    *(unsigned*)&hs[16 * mb + qr][c] =
                        packh2(C[mb][nt][0] + bb0, C[mb][nt][1] + bb1);
                    *(unsigned*)&hs[16 * mb + qr + 8][c] =
                        packh2(C[mb][nt][2] + bb0, C[mb][nt][3] + bb1);
                }
            }
        }
        __syncthreads();   // next GEMM reads all columns

        if (layer == 0) {
            // ---- layer 2 GEMM + scores ----
            float C[2][4][4];
            float Cs[2][4];
#pragma unroll
            for (int mb = 0; mb < 2; mb++) {
#pragma unroll
                for (int nt = 0; nt < 4; nt++)
#pragma unroll
                    for (int i = 0; i < 4; i++) C[mb][nt][i] = 0.f;
#pragma unroll
                for (int i = 0; i < 4; i++) Cs[mb][i] = 0.f;
            }

            const uint4* W2h4 = (const uint4*)W2h_g;
            const uint4* U2f4 = (const uint4*)U2f_g;
#pragma unroll
            for (int m = 0; m < 4; m++) {
                uint4 wv[4];
#pragma unroll
                for (int nt = 0; nt < 4; nt++)
                    wv[nt] = W2h4[((w * 4 + nt) * 4 + m) * 32 + lane];
                uint4 uv = U2f4[m * 32 + lane];
#pragma unroll
                for (int hh = 0; hh < 2; hh++) {
                    const int kt = 2 * m + hh;
                    unsigned a[2][4];
#pragma unroll
                    for (int mb = 0; mb < 2; mb++) {
                        const int r0 = 16 * mb + qr;
                        a[mb][0] = *(const unsigned*)&hs[r0][16 * kt + 2 * qc];
                        a[mb][1] = *(const unsigned*)&hs[r0 + 8][16 * kt + 2 * qc];
                        a[mb][2] = *(const unsigned*)&hs[r0][16 * kt + 2 * qc + 8];
                        a[mb][3] = *(const unsigned*)&hs[r0 + 8][16 * kt + 2 * qc + 8];
                    }
#pragma unroll
                    for (int nt = 0; nt < 4; nt++) {
                        unsigned bf[2];
                        if (hh == 0) { bf[0] = wv[nt].x; bf[1] = wv[nt].y; }
                        else         { bf[0] = wv[nt].z; bf[1] = wv[nt].w; }
#pragma unroll
                        for (int mb = 0; mb < 2; mb++) mma_h(C[mb][nt], a[mb], bf);
                    }
                    {
                        unsigned bf[2];
                        if (hh == 0) { bf[0] = uv.x; bf[1] = uv.y; }
                        else         { bf[0] = uv.z; bf[1] = uv.w; }
#pragma unroll
                        for (int mb = 0; mb < 2; mb++) mma_h(Cs[mb], a[mb], bf);
                    }
                }
            }
            __syncthreads();   // all warps done reading hs before overwrite
#pragma unroll
            for (int mb = 0; mb < 2; mb++)
#pragma unroll
                for (int nt = 0; nt < 4; nt++) {
                    const int c = 32 * w + 8 * nt + 2 * qc;
                    *(unsigned*)&hs[16 * mb + qr][c]     = packh2(C[mb][nt][0], C[mb][nt][1]);
                    *(unsigned*)&hs[16 * mb + qr + 8][c] = packh2(C[mb][nt][2], C[mb][nt][3]);
                }
            store_scores(Cs, s_src, s_dst, w, qr, qc);
        } else {
            // ---- layer 3 GEMM (padded cols 8w..8w+7) + scores ----
            float C[2][4];
            float Cs[2][4];
#pragma unroll
            for (int mb = 0; mb < 2; mb++)
#pragma unroll
                for (int i = 0; i < 4; i++) { C[mb][i] = 0.f; Cs[mb][i] = 0.f; }

            const uint4* W3h4 = (const uint4*)W3h_g;
            const uint4* U3f4 = (const uint4*)U3f_g;
#pragma unroll
            for (int m = 0; m < 4; m++) {
                uint4 wv = W3h4[(w * 4 + m) * 32 + lane];
                uint4 uv = U3f4[m * 32 + lane];
#pragma unroll
                for (int hh = 0; hh < 2; hh++) {
                    const int kt = 2 * m + hh;
                    unsigned a[2][4];
#pragma unroll
                    for (int mb = 0; mb < 2; mb++) {
                        const int r0 = 16 * mb + qr;
                        a[mb][0] = *(const unsigned*)&hs[r0][16 * kt + 2 * qc];
                        a[mb][1] = *(const unsigned*)&hs[r0 + 8][16 * kt + 2 * qc];
                        a[mb][2] = *(const unsigned*)&hs[r0][16 * kt + 2 * qc + 8];
                        a[mb][3] = *(const unsigned*)&hs[r0 + 8][16 * kt + 2 * qc + 8];
                    }
                    unsigned bf[2], bu[2];
                    if (hh == 0) { bf[0] = wv.x; bf[1] = wv.y; bu[0] = uv.x; bu[1] = uv.y; }
                    else         { bf[0] = wv.z; bf[1] = wv.w; bu[0] = uv.z; bu[1] = uv.w; }
#pragma unroll
                    for (int mb = 0; mb < 2; mb++) {
                        mma_h(C[mb], a[mb], bf);
                        mma_h(Cs[mb], a[mb], bu);
                    }
                }
            }
            __syncthreads();   // all warps done reading hs before writing cols 0..31
#pragma unroll
            for (int mb = 0; mb < 2; mb++) {
                const int c = 8 * w + 2 * qc;
                *(unsigned*)&hs[16 * mb + qr][c]     = packh2(C[mb][0], C[mb][1]);
                *(unsigned*)&hs[16 * mb + qr + 8][c] = packh2(C[mb][2], C[mb][3]);
            }
            store_scores(Cs, s_src, s_dst, w, qr, qc);
        }
    }
    __syncwarp();

    // ================= layer-3 attention + register tail =================
    {
        const int cp = 8 * w;

        // softmax (scores from GEMM3 epilogue)
        {
            const float sdst = s_dst[w * NCOL + lane];
            float e[NCOL];
            float m = -1e30f;
#pragma unroll
            for (int q = 0; q < 8; q++) {
                float4 sv = *(const float4*)&s_src[w * NCOL + 4 * q];
                e[4*q+0] = lrelu(sdst + sv.x);
                e[4*q+1] = lrelu(sdst + sv.y);
                e[4*q+2] = lrelu(sdst + sv.z);
                e[4*q+3] = lrelu(sdst + sv.w);
            }
#pragma unroll
            for (int j = 0; j < NCOL; j++) m = fmaxf(m, e[j]);
            float sum = 0.f;
#pragma unroll
            for (int j = 0; j < NCOL; j++) {
                e[j] = __expf(e[j] - m);
                sum += e[j];
            }
            const float rinv = 1.f / sum;
#pragma unroll
            for (int q = 0; q < 4; q++) {
                uint4 v;
                v.x = packh2(e[8*q+0] * rinv, e[8*q+1] * rinv);
                v.y = packh2(e[8*q+2] * rinv, e[8*q+3] * rinv);
                v.z = packh2(e[8*q+4] * rinv, e[8*q+5] * rinv);
                v.w = packh2(e[8*q+6] * rinv, e[8*q+7] * rinv);
                *(uint4*)&alphas[w][lane][4 * q] = v;
            }
        }
        __syncwarp();

        // MMA: h3post = alpha @ h3 (N=8 padded); C stays in registers
        float C[2][4];
#pragma unroll
        for (int mb = 0; mb < 2; mb++)
#pragma unroll
            for (int i = 0; i < 4; i++) C[mb][i] = 0.f;

        unsigned af[2][2][4];
#pragma unroll
        for (int kt = 0; kt < 2; kt++)
#pragma unroll
            for (int mb = 0; mb < 2; mb++) {
                const int r0 = 16 * mb + qr;
                af[kt][mb][0] = alphas[w][r0][8 * kt + qc];
                af[kt][mb][1] = alphas[w][r0 + 8][8 * kt + qc];
                af[kt][mb][2] = alphas[w][r0][8 * kt + qc + 4];
                af[kt][mb][3] = alphas[w][r0 + 8][8 * kt + qc + 4];
            }
        {
            unsigned d0, d1, d2, d3;
            ldsm_x4_trans(d0, d1, d2, d3, sptr(&hs[lane][cp]));
            unsigned bf0[2] = { d0, d1 };
            unsigned bf1[2] = { d2, d3 };
#pragma unroll
            for (int mb = 0; mb < 2; mb++) {
                mma_h(C[mb], af[0][mb], bf0);
                mma_h(C[mb], af[1][mb], bf1);
            }
        }

        // tail: node-mean of h3post directly from C fragments
        float se = C[0][0] + C[0][2] + C[1][0] + C[1][2];   // col cp+2qc
        float so = C[0][1] + C[0][3] + C[1][1] + C[1][3];   // col cp+2qc+1
        u64 p = pack2(se, so);
        add2(p, shfl_xor_u64(p, 4));
        add2(p, shfl_xor_u64(p, 8));
        add2(p, shfl_xor_u64(p, 16));
        if (qr == 0 && qc < 3) {
            float2 pv = unpack2(p);
            cs[w * 6 + 2 * qc]     = pv.x * (1.f / 32.f) + b3[w * 6 + 2 * qc];
            cs[w * 6 + 2 * qc + 1] = pv.y * (1.f / 32.f) + b3[w * 6 + 2 * qc + 1];
        }
    }
    __syncthreads();

    // ---- final linear ----
    if (t < 64) {
        float acc = lb[t];
#pragma unroll
        for (int k = 0; k < F3; k++) acc = fmaf(cs[k], lw[k * 64 + t], acc);
        out[(size_t)g * 64 + t] = acc;
    }
}

extern "C" void kernel_launch(void* const* d_in, const int* in_sizes, int n_in,
                              void* d_out, int out_size)
{
    const float* xs  = (const float*)d_in[0];
    const float* pe  = (const float*)d_in[1];
    const float* W1  = (const float*)d_in[2];
    const float* as1 = (const float*)d_in[3];
    const float* ad1 = (const float*)d_in[4];
    const float* b1  = (const float*)d_in[5];
    const float* W2  = (const float*)d_in[6];
    const float* as2 = (const float*)d_in[7];
    const float* ad2 = (const float*)d_in[8];
    const float* b2  = (const float*)d_in[9];
    const float* W3  = (const float*)d_in[10];
    const float* as3 = (const float*)d_in[11];
    const float* ad3 = (const float*)d_in[12];
    const float* b3  = (const float*)d_in[13];
    const float* lw  = (const float*)d_in[14];
    const float* lb  = (const float*)d_in[15];
    float* out = (float*)d_out;

    int B = in_sizes[1] / (32 * 15);
    int R = in_sizes[0] / (B * 32);
    int G = B * R;

    prep_kernel<<<97, 128>>>(W1, W2, W3, as1, ad1, as2, ad2, as3, ad3);
    gat_fused_kernel<<<G, THREADS>>>(xs, pe, b1, b2, b3, lw, lb, out, R);
}

// round 14
// speedup vs baseline: 3.9354x; 1.0020x over previous
#include <cuda_runtime.h>
#include <cuda_fp16.h>

// GAT over 16384 independent 32-node cliques, fully fused: one CTA per graph.
// fp16 tensor cores for all products; scores folded into GEMMs; ALL fragment
// loads (A via ldmatrix.x4, B via ldmatrix.x4.trans) — no scalar LDS in the
// hot path. Softmax: fp32, no max-pass (scores are O(1); exp is safe).

#define NCOL 32
#define HEADS 4
#define FH 128
#define HSTR 136        // hs row stride in halfs (272B; 68 words = 4 mod 32)
#define F3 24
#define XSTR 24         // xin row stride in halfs (12 words mod 32: conflict-free)
#define ASTRW 20        // alpha row stride in u32 words (20 mod 32: conflict-free)
#define THREADS 128
#define NEG_SLOPE 0.2f

typedef unsigned long long u64;

__device__ unsigned W2h_g[8192];   // fragment-ordered fp16x2 weights
__device__ unsigned W1h_g[1024];
__device__ unsigned W3h_g[2048];
__device__ unsigned U1f_g[64];     // fragment-ordered score vectors (W @ a)
__device__ unsigned U2f_g[512];
__device__ unsigned U3f_g[512];

__device__ __forceinline__ float lrelu(float x) { return fmaxf(x, NEG_SLOPE * x); }

__device__ __forceinline__ u64 pack2(float a, float b) {
    u64 r; asm("mov.b64 %0,{%1,%2};" : "=l"(r) : "f"(a), "f"(b)); return r;
}
__device__ __forceinline__ float2 unpack2(u64 v) {
    float2 r; asm("mov.b64 {%0,%1},%2;" : "=f"(r.x), "=f"(r.y) : "l"(v)); return r;
}
__device__ __forceinline__ void add2(u64 &d, u64 a) {
    asm("add.rn.f32x2 %0,%0,%1;" : "+l"(d) : "l"(a));
}
__device__ __forceinline__ u64 shfl_xor_u64(u64 v, int m) {
    unsigned lo, hi;
    asm("mov.b64 {%0,%1},%2;" : "=r"(lo), "=r"(hi) : "l"(v));
    lo = __shfl_xor_sync(0xffffffffu, lo, m);
    hi = __shfl_xor_sync(0xffffffffu, hi, m);
    u64 r; asm("mov.b64 %0,{%1,%2};" : "=l"(r) : "r"(lo), "r"(hi));
    return r;
}
__device__ __forceinline__ unsigned packh2(float lo, float hi) {
    __half2 h = __floats2half2_rn(lo, hi);
    return *(unsigned*)&h;
}
__device__ __forceinline__ void mma_h(float c[4], const unsigned a[4], const unsigned b[2]) {
    asm("mma.sync.aligned.m16n8k16.row.col.f32.f16.f16.f32 "
        "{%0,%1,%2,%3}, {%4,%5,%6,%7}, {%8,%9}, {%0,%1,%2,%3};"
        : "+f"(c[0]), "+f"(c[1]), "+f"(c[2]), "+f"(c[3])
        : "r"(a[0]), "r"(a[1]), "r"(a[2]), "r"(a[3]), "r"(b[0]), "r"(b[1]));
}
__device__ __forceinline__ unsigned sptr(const void* p) {
    unsigned a;
    asm("{ .reg .u64 t; cvta.to.shared.u64 t, %1; cvt.u32.u64 %0, t; }" : "=r"(a) : "l"(p));
    return a;
}
__device__ __forceinline__ void ldsm_x4_trans(unsigned &d0, unsigned &d1,
                                              unsigned &d2, unsigned &d3, unsigned addr) {
    asm volatile("ldmatrix.sync.aligned.m8n8.x4.trans.shared.b16 {%0,%1,%2,%3}, [%4];"
                 : "=r"(d0), "=r"(d1), "=r"(d2), "=r"(d3) : "r"(addr));
}
__device__ __forceinline__ void ldsm_x4(unsigned a[4], unsigned addr) {
    asm volatile("ldmatrix.sync.aligned.m8n8.x4.shared.b16 {%0,%1,%2,%3}, [%4];"
                 : "=r"(a[0]), "=r"(a[1]), "=r"(a[2]), "=r"(a[3]) : "r"(addr));
}

// Scatter the 8-column score tile (C fragments) to s_src/s_dst for head w.
__device__ __forceinline__ void store_scores(const float Cs[2][4],
                                             float* __restrict__ s_src,
                                             float* __restrict__ s_dst,
                                             int w, int qr, int qc)
{
    const int par = w & 1;
    if (qc == (w >> 1)) {
        s_src[32 * w + qr]      = par ? Cs[0][1] : Cs[0][0];
        s_src[32 * w + qr + 8]  = par ? Cs[0][3] : Cs[0][2];
        s_src[32 * w + qr + 16] = par ? Cs[1][1] : Cs[1][0];
        s_src[32 * w + qr + 24] = par ? Cs[1][3] : Cs[1][2];
    }
    if (qc == 2 + (w >> 1)) {
        s_dst[32 * w + qr]      = par ? Cs[0][1] : Cs[0][0];
        s_dst[32 * w + qr + 8]  = par ? Cs[0][3] : Cs[0][2];
        s_dst[32 * w + qr + 16] = par ? Cs[1][1] : Cs[1][0];
        s_dst[32 * w + qr + 24] = par ? Cs[1][3] : Cs[1][2];
    }
}

__global__ void prep_kernel(const float* __restrict__ W1, const float* __restrict__ W2,
                            const float* __restrict__ W3,
                            const float* __restrict__ as1, const float* __restrict__ ad1,
                            const float* __restrict__ as2, const float* __restrict__ ad2,
                            const float* __restrict__ as3, const float* __restrict__ ad3)
{
    int idx = blockIdx.x * blockDim.x + threadIdx.x;
    if (idx < 8192) {            // W2h: (((w*4+nt)*4+m)*32+lane)*4+j
        int j = idx & 3, lane = (idx >> 2) & 31, m = (idx >> 7) & 3, unit = idx >> 9;
        int qr = lane >> 2, qc = lane & 3;
        int w = unit >> 2, nt = unit & 3;
        int kt = 2 * m + (j >> 1);
        int kp = 16 * kt + 2 * qc + ((j & 1) ? 8 : 0);
        int col = 32 * w + 8 * nt + qr;
        W2h_g[idx] = packh2(W2[kp * FH + col], W2[(kp + 1) * FH + col]);
    } else if (idx < 9216) {     // W1h
        int i = idx - 8192;
        int j = i & 1, lane = (i >> 1) & 31, unit = i >> 6;
        int qr = lane >> 2, qc = lane & 3;
        int w = unit >> 2, nt = unit & 3;
        int kp = 2 * qc + (j ? 8 : 0);
        int col = 32 * w + 8 * nt + qr;
        W1h_g[i] = packh2(W1[kp * FH + col], W1[(kp + 1) * FH + col]);
    } else if (idx < 11264) {    // W3h (padded n=qr, zero qr>=6)
        int i = idx - 9216;
        int j = i & 3, lane = (i >> 2) & 31, m = (i >> 7) & 3, w = i >> 9;
        int qr = lane >> 2, qc = lane & 3;
        int kt = 2 * m + (j >> 1);
        int kp = 16 * kt + 2 * qc + ((j & 1) ? 8 : 0);
        W3h_g[i] = (qr < 6) ? packh2(W3[kp * F3 + w * 6 + qr], W3[(kp + 1) * F3 + w * 6 + qr]) : 0u;
    } else if (idx < 11776) {    // U2f
        int i = idx - 11264;
        int jj = i & 3, lane = (i >> 2) & 31, m = i >> 7;
        int qr = lane >> 2, qc = lane & 3;
        int kt = 2 * m + (jj >> 1);
        int kp = 16 * kt + 2 * qc + ((jj & 1) ? 8 : 0);
        const float* av = (qr < 4) ? (as2 + 32 * qr) : (ad2 + 32 * (qr - 4));
        int h = qr & 3;
        float u0 = 0.f, u1 = 0.f;
        for (int d = 0; d < 32; d++) {
            u0 += W2[kp * FH + 32 * h + d] * av[d];
            u1 += W2[(kp + 1) * FH + 32 * h + d] * av[d];
        }
        U2f_g[i] = packh2(u0, u1);
    } else if (idx < 11840) {    // U1f
        int i = idx - 11776;
        int jj = i & 1, lane = i >> 1;
        int qr = lane >> 2, qc = lane & 3;
        int kp = 2 * qc + (jj ? 8 : 0);
        const float* av = (qr < 4) ? (as1 + 32 * qr) : (ad1 + 32 * (qr - 4));
        int h = qr & 3;
        float u0 = 0.f, u1 = 0.f;
        for (int d = 0; d < 32; d++) {
            u0 += W1[kp * FH + 32 * h + d] * av[d];
            u1 += W1[(kp + 1) * FH + 32 * h + d] * av[d];
        }
        U1f_g[i] = packh2(u0, u1);
    } else if (idx < 12352) {    // U3f
        int i = idx - 11840;
        int jj = i & 3, lane = (i >> 2) & 31, m = i >> 7;
        int qr = lane >> 2, qc = lane & 3;
        int kt = 2 * m + (jj >> 1);
        int kp = 16 * kt + 2 * qc + ((jj & 1) ? 8 : 0);
        const float* av = (qr < 4) ? (as3 + 6 * qr) : (ad3 + 6 * (qr - 4));
        int h = qr & 3;
        float u0 = 0.f, u1 = 0.f;
        for (int d = 0; d < 6; d++) {
            u0 += W3[kp * F3 + 6 * h + d] * av[d];
            u1 += W3[(kp + 1) * F3 + 6 * h + d] * av[d];
        }
        U3f_g[i] = packh2(u0, u1);
    }
}

__global__ void __launch_bounds__(THREADS, 6) gat_fused_kernel(
    const float* __restrict__ xs,
    const float* __restrict__ pe,
    const float* __restrict__ b1,
    const float* __restrict__ b2,
    const float* __restrict__ b3,
    const float* __restrict__ lw,
    const float* __restrict__ lb,
    float* __restrict__ out,
    int R)
{
    __shared__ __half hs[NCOL][HSTR];
    __shared__ unsigned alphas[HEADS][NCOL][ASTRW];
    __shared__ float s_src[HEADS * NCOL];
    __shared__ float s_dst[HEADS * NCOL];
    __shared__ float cs[F3];

    __half (*xin)[XSTR] = (__half(*)[XSTR]) & alphas[0][0][0];  // overlay

    const int g = blockIdx.x;
    const int b = g / R;
    const int r = g - b * R;
    const int t = threadIdx.x;
    const int lane = t & 31;
    const int w = t >> 5;
    const int qr = lane >> 2;
    const int qc = lane & 3;
    const int lrow = lane & 15;                 // ldmatrix A row-within-tile
    const int lkoff = (lane >> 4) << 3;         // ldmatrix A k-half offset (0 or 8)

    // ---- build input features (fp16) ----
    for (int idx = t; idx < NCOL * 16; idx += THREADS) {
        int n = idx >> 4, f = idx & 15;
        float v;
        if (f == 0) v = xs[(size_t)(b * R + r) * NCOL + n];
        else        v = pe[(b * NCOL + n) * 15 + (f - 1)];
        xin[n][f] = __float2half_rn(v);
    }
    __syncthreads();

    // ================= layer 1 GEMM + scores =================
    {
        float C[2][4][4];
        float Cs[2][4];
#pragma unroll
        for (int mb = 0; mb < 2; mb++) {
#pragma unroll
            for (int nt = 0; nt < 4; nt++)
#pragma unroll
                for (int i = 0; i < 4; i++) C[mb][nt][i] = 0.f;
#pragma unroll
            for (int i = 0; i < 4; i++) Cs[mb][i] = 0.f;
        }

        unsigned a[2][4];
#pragma unroll
        for (int mb = 0; mb < 2; mb++)
            ldsm_x4(a[mb], sptr(&xin[16 * mb + lrow][lkoff]));

        const uint2* W1h2 = (const uint2*)W1h_g;
#pragma unroll
        for (int nt = 0; nt < 4; nt++) {
            uint2 bw = W1h2[(w * 4 + nt) * 32 + lane];
            unsigned bf[2] = { bw.x, bw.y };
#pragma unroll
            for (int mb = 0; mb < 2; mb++) mma_h(C[mb][nt], a[mb], bf);
        }
        {
            uint2 uw = ((const uint2*)U1f_g)[lane];
            unsigned bf[2] = { uw.x, uw.y };
#pragma unroll
            for (int mb = 0; mb < 2; mb++) mma_h(Cs[mb], a[mb], bf);
        }
#pragma unroll
        for (int mb = 0; mb < 2; mb++)
#pragma unroll
            for (int nt = 0; nt < 4; nt++) {
                const int c = 32 * w + 8 * nt + 2 * qc;
                *(unsigned*)&hs[16 * mb + qr][c]     = packh2(C[mb][nt][0], C[mb][nt][1]);
                *(unsigned*)&hs[16 * mb + qr + 8][c] = packh2(C[mb][nt][2], C[mb][nt][3]);
            }
        store_scores(Cs, s_src, s_dst, w, qr, qc);
    }
    __syncthreads();   // xin reads done -> alphas writable; hs + scores visible

    // ================= attention layers 1 & 2 + following GEMM =================
#pragma unroll
    for (int layer = 0; layer < 2; layer++) {
        const float* bias = layer ? b2 : b1;
        const int c0 = 32 * w;
        __syncwarp();

        // softmax (no max-pass: scores are O(1), fp32 exp is safe)
        {
            const float sdst = s_dst[w * NCOL + lane];
            float e[NCOL];
            float sum = 0.f;
#pragma unroll
            for (int q = 0; q < 8; q++) {
                float4 sv = *(const float4*)&s_src[w * NCOL + 4 * q];
                e[4*q+0] = __expf(lrelu(sdst + sv.x));
                e[4*q+1] = __expf(lrelu(sdst + sv.y));
                e[4*q+2] = __expf(lrelu(sdst + sv.z));
                e[4*q+3] = __expf(lrelu(sdst + sv.w));
                sum += e[4*q+0] + e[4*q+1] + e[4*q+2] + e[4*q+3];
            }
            const float rinv = 1.f / sum;
#pragma unroll
            for (int q = 0; q < 4; q++) {
                uint4 v;
                v.x = packh2(e[8*q+0] * rinv, e[8*q+1] * rinv);
                v.y = packh2(e[8*q+2] * rinv, e[8*q+3] * rinv);
                v.z = packh2(e[8*q+4] * rinv, e[8*q+5] * rinv);
                v.w = packh2(e[8*q+6] * rinv, e[8*q+7] * rinv);
                *(uint4*)&alphas[w][lane][4 * q] = v;
            }
        }
        __syncwarp();

        // aggregation MMA: out(32x32) = alpha @ h_head, in-place (warp-local cols)
        {
            float C[2][4][4];
#pragma unroll
            for (int mb = 0; mb < 2; mb++)
#pragma unroll
                for (int nt = 0; nt < 4; nt++)
#pragma unroll
                    for (int i = 0; i < 4; i++) C[mb][nt][i] = 0.f;

            unsigned af[2][2][4];
#pragma unroll
            for (int kt = 0; kt < 2; kt++)
#pragma unroll
                for (int mb = 0; mb < 2; mb++)
                    ldsm_x4(af[kt][mb],
                            sptr((const __half*)&alphas[w][16 * mb + lrow][0] + 16 * kt + lkoff));
#pragma unroll
            for (int nt = 0; nt < 4; nt++) {
                unsigned d0, d1, d2, d3;
                ldsm_x4_trans(d0, d1, d2, d3, sptr(&hs[lane][c0 + 8 * nt]));
                unsigned bf0[2] = { d0, d1 };
                unsigned bf1[2] = { d2, d3 };
#pragma unroll
                for (int mb = 0; mb < 2; mb++) {
                    mma_h(C[mb][nt], af[0][mb], bf0);
                    mma_h(C[mb][nt], af[1][mb], bf1);
                }
            }
            // epilogue: + bias, pack fp16, in-place store
#pragma unroll
            for (int nt = 0; nt < 4; nt++) {
                const int c = c0 + 8 * nt + 2 * qc;
                float bb0 = bias[c], bb1 = bias[c + 1];
#pragma unroll
                for (int mb = 0; mb < 2; mb++) {
                    *(unsigned*)&hs[16 * mb + qr][c] =
                        packh2(C[mb][nt][0] + bb0, C[mb][nt][1] + bb1);
                    *(unsigned*)&hs[16 * mb + qr + 8][c] =
                        packh2(C[mb][nt][2] + bb0, C[mb][nt][3] + bb1);
                }
            }
        }
        __syncthreads();   // next GEMM reads all columns

        if (layer == 0) {
            // ---- layer 2 GEMM + scores ----
            float C[2][4][4];
            float Cs[2][4];
#pragma unroll
            for (int mb = 0; mb < 2; mb++) {
#pragma unroll
                for (int nt = 0; nt < 4; nt++)
#pragma unroll
                    for (int i = 0; i < 4; i++) C[mb][nt][i] = 0.f;
#pragma unroll
                for (int i = 0; i < 4; i++) Cs[mb][i] = 0.f;
            }

            const uint4* W2h4 = (const uint4*)W2h_g;
            const uint4* U2f4 = (const uint4*)U2f_g;
#pragma unroll
            for (int m = 0; m < 4; m++) {
                uint4 wv[4];
#pragma unroll
                for (int nt = 0; nt < 4; nt++)
                    wv[nt] = W2h4[((w * 4 + nt) * 4 + m) * 32 + lane];
                uint4 uv = U2f4[m * 32 + lane];
#pragma unroll
                for (int hh = 0; hh < 2; hh++) {
                    const int kt = 2 * m + hh;
                    unsigned a[2][4];
#pragma unroll
                    for (int mb = 0; mb < 2; mb++)
                        ldsm_x4(a[mb], sptr(&hs[16 * mb + lrow][16 * kt + lkoff]));
#pragma unroll
                    for (int nt = 0; nt < 4; nt++) {
                        unsigned bf[2];
                        if (hh == 0) { bf[0] = wv[nt].x; bf[1] = wv[nt].y; }
                        else         { bf[0] = wv[nt].z; bf[1] = wv[nt].w; }
#pragma unroll
                        for (int mb = 0; mb < 2; mb++) mma_h(C[mb][nt], a[mb], bf);
                    }
                    {
                        unsigned bf[2];
                        if (hh == 0) { bf[0] = uv.x; bf[1] = uv.y; }
                        else         { bf[0] = uv.z; bf[1] = uv.w; }
#pragma unroll
                        for (int mb = 0; mb < 2; mb++) mma_h(Cs[mb], a[mb], bf);
                    }
                }
            }
            __syncthreads();   // all warps done reading hs before overwrite
#pragma unroll
            for (int mb = 0; mb < 2; mb++)
#pragma unroll
                for (int nt = 0; nt < 4; nt++) {
                    const int c = 32 * w + 8 * nt + 2 * qc;
                    *(unsigned*)&hs[16 * mb + qr][c]     = packh2(C[mb][nt][0], C[mb][nt][1]);
                    *(unsigned*)&hs[16 * mb + qr + 8][c] = packh2(C[mb][nt][2], C[mb][nt][3]);
                }
            store_scores(Cs, s_src, s_dst, w, qr, qc);
        } else {
            // ---- layer 3 GEMM (padded cols 8w..8w+7) + scores ----
            float C[2][4];
            float Cs[2][4];
#pragma unroll
            for (int mb = 0; mb < 2; mb++)
#pragma unroll
                for (int i = 0; i < 4; i++) { C[mb][i] = 0.f; Cs[mb][i] = 0.f; }

            const uint4* W3h4 = (const uint4*)W3h_g;
            const uint4* U3f4 = (const uint4*)U3f_g;
#pragma unroll
            for (int m = 0; m < 4; m++) {
                uint4 wv = W3h4[(w * 4 + m) * 32 + lane];
                uint4 uv = U3f4[m * 32 + lane];
#pragma unroll
                for (int hh = 0; hh < 2; hh++) {
                    const int kt = 2 * m + hh;
                    unsigned a[2][4];
#pragma unroll
                    for (int mb = 0; mb < 2; mb++)
                        ldsm_x4(a[mb], sptr(&hs[16 * mb + lrow][16 * kt + lkoff]));
                    unsigned bf[2], bu[2];
                    if (hh == 0) { bf[0] = wv.x; bf[1] = wv.y; bu[0] = uv.x; bu[1] = uv.y; }
                    else         { bf[0] = wv.z; bf[1] = wv.w; bu[0] = uv.z; bu[1] = uv.w; }
#pragma unroll
                    for (int mb = 0; mb < 2; mb++) {
                        mma_h(C[mb], a[mb], bf);
                        mma_h(Cs[mb], a[mb], bu);
                    }
                }
            }
            __syncthreads();   // all warps done reading hs before writing cols 0..31
#pragma unroll
            for (int mb = 0; mb < 2; mb++) {
                const int c = 8 * w + 2 * qc;
                *(unsigned*)&hs[16 * mb + qr][c]     = packh2(C[mb][0], C[mb][1]);
                *(unsigned*)&hs[16 * mb + qr + 8][c] = packh2(C[mb][2], C[mb][3]);
            }
            store_scores(Cs, s_src, s_dst, w, qr, qc);
        }
    }
    __syncwarp();

    // ================= layer-3 attention + register tail =================
    {
        const int cp = 8 * w;

        // softmax (no max-pass)
        {
            const float sdst = s_dst[w * NCOL + lane];
            float e[NCOL];
            float sum = 0.f;
#pragma unroll
            for (int q = 0; q < 8; q++) {
                float4 sv = *(const float4*)&s_src[w * NCOL + 4 * q];
                e[4*q+0] = __expf(lrelu(sdst + sv.x));
                e[4*q+1] = __expf(lrelu(sdst + sv.y));
                e[4*q+2] = __expf(lrelu(sdst + sv.z));
                e[4*q+3] = __expf(lrelu(sdst + sv.w));
                sum += e[4*q+0] + e[4*q+1] + e[4*q+2] + e[4*q+3];
            }
            const float rinv = 1.f / sum;
#pragma unroll
            for (int q = 0; q < 4; q++) {
                uint4 v;
                v.x = packh2(e[8*q+0] * rinv, e[8*q+1] * rinv);
                v.y = packh2(e[8*q+2] * rinv, e[8*q+3] * rinv);
                v.z = packh2(e[8*q+4] * rinv, e[8*q+5] * rinv);
                v.w = packh2(e[8*q+6] * rinv, e[8*q+7] * rinv);
                *(uint4*)&alphas[w][lane][4 * q] = v;
            }
        }
        __syncwarp();

        // MMA: h3post = alpha @ h3 (N=8 padded); C stays in registers
        float C[2][4];
#pragma unroll
        for (int mb = 0; mb < 2; mb++)
#pragma unroll
            for (int i = 0; i < 4; i++) C[mb][i] = 0.f;

        unsigned af[2][2][4];
#pragma unroll
        for (int kt = 0; kt < 2; kt++)
#pragma unroll
            for (int mb = 0; mb < 2; mb++)
                ldsm_x4(af[kt][mb],
                        sptr((const __half*)&alphas[w][16 * mb + lrow][0] + 16 * kt + lkoff));
        {
            unsigned d0, d1, d2, d3;
            ldsm_x4_trans(d0, d1, d2, d3, sptr(&hs[lane][cp]));
            unsigned bf0[2] = { d0, d1 };
            unsigned bf1[2] = { d2, d3 };
#pragma unroll
            for (int mb = 0; mb < 2; mb++) {
                mma_h(C[mb], af[0][mb], bf0);
                mma_h(C[mb], af[1][mb], bf1);
            }
        }

        // tail: node-mean of h3post directly from C fragments
        float se = C[0][0] + C[0][2] + C[1][0] + C[1][2];
        float so = C[0][1] + C[0][3] + C[1][1] + C[1][3];
        u64 p = pack2(se, so);
        add2(p, shfl_xor_u64(p, 4));
        add2(p, shfl_xor_u64(p, 8));
        add2(p, shfl_xor_u64(p, 16));
        if (qr == 0 && qc < 3) {
            float2 pv = unpack2(p);
            cs[w * 6 + 2 * qc]     = pv.x * (1.f / 32.f) + b3[w * 6 + 2 * qc];
            cs[w * 6 + 2 * qc + 1] = pv.y * (1.f / 32.f) + b3[w * 6 + 2 * qc + 1];
        }
    }
    __syncthreads();

    // ---- final linear ----
    if (t < 64) {
        float acc = lb[t];
#pragma unroll
        for (int k = 0; k < F3; k++) acc = fmaf(cs[k], lw[k * 64 + t], acc);
        out[(size_t)g * 64 + t] = acc;
    }
}

extern "C" void kernel_launch(void* const* d_in, const int* in_sizes, int n_in,
                              void* d_out, int out_size)
{
    const float* xs  = (const float*)d_in[0];
    const float* pe  = (const float*)d_in[1];
    const float* W1  = (const float*)d_in[2];
    const float* as1 = (const float*)d_in[3];
    const float* ad1 = (const float*)d_in[4];
    const float* b1  = (const float*)d_in[5];
    const float* W2  = (const float*)d_in[6];
    const float* as2 = (const float*)d_in[7];
    const float* ad2 = (const float*)d_in[8];
    const float* b2  = (const float*)d_in[9];
    const float* W3  = (const float*)d_in[10];
    const float* as3 = (const float*)d_in[11];
    const float* ad3 = (const float*)d_in[12];
    const float* b3  = (const float*)d_in[13];
    const float* lw  = (const float*)d_in[14];
    const float* lb  = (const float*)d_in[15];
    float* out = (float*)d_out;

    int B = in_sizes[1] / (32 * 15);
    int R = in_sizes[0] / (B * 32);
    int G = B * R;

    prep_kernel<<<97, 128>>>(W1, W2, W3, as1, ad1, as2, ad2, as3, ad3);
    gat_fused_kernel<<<G, THREADS>>>(xs, pe, b1, b2, b3, lw, lb, out, R);
}